// round 6
// baseline (speedup 1.0000x reference)
#include <cuda_runtime.h>
#include <cuda_bf16.h>
#include <math.h>
#include <stdint.h>

#define NE    50000
#define DIM   200
#define BATCH 1024
#define EMAX  400000
#define RELD  40000
#define KPAD  256          // [data(200) | zero-pad(56)]
#define NCHUNK 4
#define NPAD  256

// ---------------- scratch (zero-init => pad regions stay 0)
__device__ __align__(16) __nv_bfloat16 g_e0b[(size_t)NE*KPAD];
__device__ __align__(16) __nv_bfloat16 g_hrb[(size_t)BATCH*KPAD];
__device__ __align__(16) __nv_bfloat16 g_Wtb[(size_t)4*NPAD*KPAD]; // combined 1024 x KPAD
__device__ __align__(4) __nv_bfloat16 g_Hb[(size_t)2*NE*DIM];
__device__ __align__(4) __nv_bfloat16 g_Ub[(size_t)NE*DIM];
__device__ __align__(4) __nv_bfloat16 g_Vb[(size_t)NE*DIM];
__device__ float g_X1[NE*DIM];
__device__ float g_X2[NE*DIM];
__device__ float g_MP[NE*DIM];
__device__ float g_NMASK[2*NE];
__device__ float g_NEWEDGE[EMAX];
__device__ int   g_rp_adj[NE+1];
__device__ int   g_rp_rw [NE+1];

// ================= helpers =================
__device__ __forceinline__ uint32_t smem_u32(const void* p) {
    uint32_t a;
    asm("{ .reg .u64 t; cvta.to.shared.u64 t, %1; cvt.u32.u64 %0, t; }" : "=r"(a) : "l"(p));
    return a;
}
#define SW128(o) ((o) ^ (((o) >> 3) & 0x70))

__device__ __forceinline__ void ldmx4(uint32_t* r, uint32_t addr) {
    asm volatile("ldmatrix.sync.aligned.m8n8.x4.shared.b16 {%0,%1,%2,%3}, [%4];"
        : "=r"(r[0]), "=r"(r[1]), "=r"(r[2]), "=r"(r[3]) : "r"(addr));
}
__device__ __forceinline__ void mma16816(float* c, const uint32_t* a, const uint32_t* b) {
    asm volatile("mma.sync.aligned.m16n8k16.row.col.f32.bf16.bf16.f32 "
        "{%0,%1,%2,%3}, {%4,%5,%6,%7}, {%8,%9}, {%0,%1,%2,%3};"
        : "+f"(c[0]), "+f"(c[1]), "+f"(c[2]), "+f"(c[3])
        : "r"(a[0]), "r"(a[1]), "r"(a[2]), "r"(a[3]), "r"(b[0]), "r"(b[1]));
}
__device__ __forceinline__ void cpa16(uint32_t dst, const void* src) {
    asm volatile("cp.async.cg.shared.global [%0], [%1], 16;" :: "r"(dst), "l"(src));
}
#define CPA_COMMIT() asm volatile("cp.async.commit_group;" ::: "memory")
#define CPA_WAIT(n)  asm volatile("cp.async.wait_group %0;" :: "n"(n) : "memory")

__device__ __forceinline__ float gate_fn(float logits, float u) {
    const float bias = 1e-4f;
    float eps = (2.f*bias - 1.f)*u + (1.f - bias);
    float t = 2.f*(logf(eps) - log1pf(-eps) + logits);
    return 1.f/(1.f + expf(-t));
}
__device__ __forceinline__ float warp_sum(float v) {
    #pragma unroll
    for (int o = 16; o; o >>= 1) v += __shfl_xor_sync(0xffffffffu, v, o);
    return v;
}

// ================= conversion kernels =================
__global__ void conv_e0_k(const float* __restrict__ e0) {
    int t = blockIdx.x*blockDim.x + threadIdx.x;
    if (t >= NE*50) return;
    int row = t/50, k = (t%50)*4;
    float4 v = *(const float4*)(e0 + (size_t)row*DIM + k);
    __nv_bfloat162 p0, p1;
    p0.x = __float2bfloat16(v.x); p0.y = __float2bfloat16(v.y);
    p1.x = __float2bfloat16(v.z); p1.y = __float2bfloat16(v.w);
    __nv_bfloat16* d = g_e0b + (size_t)row*KPAD + k;
    *(__nv_bfloat162*)(d)     = p0;
    *(__nv_bfloat162*)(d + 2) = p1;
}

// W (k-major src[k][n]) -> combined Wt[1024][KPAD]
__global__ void conv_w_k(const float* __restrict__ nW1, const float* __restrict__ eW1) {
    int inst = blockIdx.y;
    int t = blockIdx.x*blockDim.x + threadIdx.x;
    if (t >= DIM*DIM) return;
    const float* src;
    if (inst == 0)      src = nW1;
    else if (inst == 1) src = nW1 + RELD;
    else if (inst == 2) src = eW1 + 2*RELD;
    else                src = eW1 + 3*RELD;
    int n = t/DIM, k = t%DIM;
    g_Wtb[(size_t)(inst*NPAD + n)*KPAD + k] = __float2bfloat16(src[(size_t)k*DIM + n]);
}

// ================= HMMA machinery (warp tile 32x64) ========================
struct WCtx {
    int aAt0, aLi0, aAt1, aLi1, aK;
    int bAt[4], bLi[4], bK;
};
__device__ __forceinline__ void wsetup(WCtx& c, int wm, int wn, int lane) {
    int i = lane >> 3, rr = lane & 7;
    int ar0 = wm*32 + (i&1)*8 + rr, ar1 = ar0 + 16;
    c.aAt0 = (ar0>>3)*1024; c.aLi0 = (ar0&7)*128;
    c.aAt1 = (ar1>>3)*1024; c.aLi1 = (ar1&7)*128;
    c.aK = (i>>1)*16;
    #pragma unroll
    for (int p = 0; p < 4; p++) {
        int br = wn*64 + p*16 + (i>>1)*8 + rr;
        c.bAt[p] = (br>>3)*1024; c.bLi[p] = (br&7)*128;
    }
    c.bK = (i&1)*16;
}
__device__ __forceinline__ void wchunk(const WCtx& c, uint32_t aA, uint32_t aB,
                                       float acc[2][8][4]) {
    #pragma unroll
    for (int ks = 0; ks < 4; ks++) {
        int kb = ks*32;
        uint32_t a0[4], a1[4], b[4][4];
        ldmx4(a0, aA + c.aAt0 + SW128(c.aLi0 + kb + c.aK));
        ldmx4(a1, aA + c.aAt1 + SW128(c.aLi1 + kb + c.aK));
        #pragma unroll
        for (int p = 0; p < 4; p++)
            ldmx4(b[p], aB + c.bAt[p] + SW128(c.bLi[p] + kb + c.bK));
        #pragma unroll
        for (int p = 0; p < 4; p++) {
            mma16816(acc[0][2*p],   a0, b[p]);
            mma16816(acc[0][2*p+1], a0, b[p] + 2);
            mma16816(acc[1][2*p],   a1, b[p]);
            mma16816(acc[1][2*p+1], a1, b[p] + 2);
        }
    }
}
// async row-tile loader into SW128 atom layout
template<int THREADS>
__device__ __forceinline__ void load_rows_async(uint32_t s, const __nv_bfloat16* G,
                                                int row0, int rmax, int c, int tid, int nrows) {
    #pragma unroll
    for (int idx = tid; idx < nrows*8; idx += THREADS) {
        int r = idx >> 3, q = idx & 7;
        int gr = row0 + r; if (gr >= rmax) gr = 0;
        uint32_t off = (uint32_t)((r>>3)*1024) + SW128((uint32_t)((r&7)*128 + q*16));
        cpa16(s + off, G + (size_t)gr*KPAD + c*64 + q*8);
    }
}

// ================= GEMM 1: combined e0 @ [W0|W1|W2|W3], BM=128 BN=128 ======
__global__ void __launch_bounds__(256) mm_e0w_k(
    const float* __restrict__ nb1, const float* __restrict__ eb1)
{
    extern __shared__ __align__(1024) uint8_t smem[];
    uint32_t aA0 = smem_u32(smem),         aA1 = smem_u32(smem + 16384);
    uint32_t aB0 = smem_u32(smem + 32768), aB1 = smem_u32(smem + 49152);
    int bm = blockIdx.x, gy = blockIdx.y;
    int tid = threadIdx.x, lane = tid & 31, w = tid >> 5;
    int wm = w >> 1, wn = w & 1;

    WCtx cx; wsetup(cx, wm, wn, lane);
    float acc[2][8][4];
    #pragma unroll
    for (int a = 0; a < 2; a++)
        #pragma unroll
        for (int b = 0; b < 8; b++)
            #pragma unroll
            for (int q = 0; q < 4; q++) acc[a][b][q] = 0.f;

    load_rows_async<256>(aA0, g_e0b, bm*128, NE, 0, tid, 128);
    load_rows_async<256>(aB0, g_Wtb, gy*128, 1024, 0, tid, 128);
    CPA_COMMIT();
    #pragma unroll
    for (int c = 0; c < NCHUNK; c++) {
        uint32_t curA = (c & 1) ? aA1 : aA0, curB = (c & 1) ? aB1 : aB0;
        if (c + 1 < NCHUNK) {
            uint32_t nxtA = ((c+1) & 1) ? aA1 : aA0, nxtB = ((c+1) & 1) ? aB1 : aB0;
            load_rows_async<256>(nxtA, g_e0b, bm*128, NE, c+1, tid, 128);
            load_rows_async<256>(nxtB, g_Wtb, gy*128, 1024, c+1, tid, 128);
            CPA_COMMIT();
            CPA_WAIT(1);
        } else {
            CPA_WAIT(0);
        }
        __syncthreads();
        wchunk(cx, curA, curB, acc);
        __syncthreads();
    }

    // epilogue -> bf16
    int inst = gy >> 1;
    int nbase = (gy & 1)*128 + wn*64;
    int mrow = lane >> 2, ncol = (lane & 3)*2;
    __nv_bfloat16* C; const float* bias; int relu = 0;
    if (inst == 0)      { C = g_Hb;               bias = nb1;        relu = 1; }
    else if (inst == 1) { C = g_Hb + (size_t)NE*DIM; bias = nb1 + DIM; relu = 1; }
    else if (inst == 2) { C = g_Ub;               bias = nullptr; }
    else                { C = g_Vb;               bias = eb1 + DIM; }

    #pragma unroll
    for (int mt = 0; mt < 2; mt++) {
        int m = bm*128 + wm*32 + mt*16 + mrow;
        if (m >= NE) continue;
        #pragma unroll
        for (int nt = 0; nt < 8; nt++) {
            int n = nbase + nt*8 + ncol;
            if (n >= DIM) continue;
            float b0 = bias ? bias[n] : 0.f, b1 = bias ? bias[n+1] : 0.f;
            float x0 = acc[mt][nt][0] + b0, x1 = acc[mt][nt][1] + b1;
            float y0 = acc[mt][nt][2] + b0, y1 = acc[mt][nt][3] + b1;
            if (relu) {
                x0 = fmaxf(x0, 0.f); x1 = fmaxf(x1, 0.f);
                y0 = fmaxf(y0, 0.f); y1 = fmaxf(y1, 0.f);
            }
            __nv_bfloat162 p; p.x = __float2bfloat16(x0); p.y = __float2bfloat16(x1);
            *(__nv_bfloat162*)(C + (size_t)m*DIM + n) = p;
            if (m + 8 < NE) {
                __nv_bfloat162 q; q.x = __float2bfloat16(y0); q.y = __float2bfloat16(y1);
                *(__nv_bfloat162*)(C + (size_t)(m+8)*DIM + n) = q;
            }
        }
    }
}

// ================= GEMM 2: scores, BM=128 BN=128, 256 threads ==============
__global__ void __launch_bounds__(256) scores_mm_k(float* __restrict__ out)
{
    extern __shared__ __align__(1024) uint8_t smem[];
    uint32_t aA0 = smem_u32(smem),         aA1 = smem_u32(smem + 16384);
    uint32_t aB0 = smem_u32(smem + 32768), aB1 = smem_u32(smem + 49152);
    int bx = blockIdx.x, by = blockIdx.y;
    int tid = threadIdx.x, lane = tid & 31, w = tid >> 5;
    int wm = w >> 1, wn = w & 1;

    WCtx cx; wsetup(cx, wm, wn, lane);
    float acc[2][8][4];
    #pragma unroll
    for (int a = 0; a < 2; a++)
        #pragma unroll
        for (int b = 0; b < 8; b++)
            #pragma unroll
            for (int q = 0; q < 4; q++) acc[a][b][q] = 0.f;

    load_rows_async<256>(aA0, g_hrb, by*128, BATCH, 0, tid, 128);
    load_rows_async<256>(aB0, g_e0b, bx*128, NE, 0, tid, 128);
    CPA_COMMIT();
    #pragma unroll
    for (int c = 0; c < NCHUNK; c++) {
        uint32_t curA = (c & 1) ? aA1 : aA0, curB = (c & 1) ? aB1 : aB0;
        if (c + 1 < NCHUNK) {
            uint32_t nxtA = ((c+1) & 1) ? aA1 : aA0, nxtB = ((c+1) & 1) ? aB1 : aB0;
            load_rows_async<256>(nxtA, g_hrb, by*128, BATCH, c+1, tid, 128);
            load_rows_async<256>(nxtB, g_e0b, bx*128, NE, c+1, tid, 128);
            CPA_COMMIT();
            CPA_WAIT(1);
        } else {
            CPA_WAIT(0);
        }
        __syncthreads();
        wchunk(cx, curA, curB, acc);
        __syncthreads();
    }

    int mrow = lane >> 2, ncol = (lane & 3)*2;
    #pragma unroll
    for (int mt = 0; mt < 2; mt++) {
        int m = by*128 + wm*32 + mt*16 + mrow;
        #pragma unroll
        for (int nt = 0; nt < 8; nt++) {
            int n = bx*128 + wn*64 + nt*8 + ncol;
            if (n < NE) {
                float2 v01, v23;
                v01.x = 1.f/(1.f + __expf(-acc[mt][nt][0]));
                v01.y = 1.f/(1.f + __expf(-acc[mt][nt][1]));
                v23.x = 1.f/(1.f + __expf(-acc[mt][nt][2]));
                v23.y = 1.f/(1.f + __expf(-acc[mt][nt][3]));
                *(float2*)(out + (size_t)m*NE + n) = v01;
                *(float2*)(out + (size_t)(m+8)*NE + n) = v23;
            }
        }
    }
}

// ================= support kernels =================
__global__ void rowptr_k(const int* __restrict__ row, int nnz, int* __restrict__ rowptr) {
    int n = blockIdx.x*blockDim.x + threadIdx.x;
    if (n > NE) return;
    int lo = 0, hi = nnz;
    while (lo < hi) { int mid = (lo+hi) >> 1; if (row[mid] < n) lo = mid+1; else hi = mid; }
    rowptr[n] = lo;
}

// node gate from bf16 H
__global__ void node_gate_k(const __nv_bfloat16* __restrict__ H, const float* __restrict__ W2,
                            const float* __restrict__ b2, const float* __restrict__ eps,
                            float* __restrict__ mask) {
    int w = (blockIdx.x*blockDim.x + threadIdx.x) >> 5;
    int lane = threadIdx.x & 31;
    if (w >= NE) return;
    const __nv_bfloat162* hr = (const __nv_bfloat162*)(H + (size_t)w*DIM);
    float acc = 0.f;
    #pragma unroll
    for (int u = 0; u < 4; u++) {
        int p = lane + 32*u;
        if (p < 100) {
            __nv_bfloat162 hv = hr[p];
            acc = fmaf(__bfloat162float(hv.x), W2[2*p],   acc);
            acc = fmaf(__bfloat162float(hv.y), W2[2*p+1], acc);
        }
    }
    acc = warp_sum(acc);
    if (lane == 0) mask[w] = gate_fn(acc + b2[0], eps[w]);
}

// edge gate from bf16 U/V
__global__ void edge_gate_k(const int* __restrict__ row, const int* __restrict__ col,
                            const float* __restrict__ adj_val,
                            const float* __restrict__ W2, const float* __restrict__ b2,
                            const float* __restrict__ eps, float* __restrict__ new_edge,
                            int E) {
    int e = (blockIdx.x*blockDim.x + threadIdx.x) >> 5;
    int lane = threadIdx.x & 31;
    if (e >= E) return;
    int r = row[e], c = col[e];
    const __nv_bfloat162* ur = (const __nv_bfloat162*)(g_Ub + (size_t)r*DIM);
    const __nv_bfloat162* vr = (const __nv_bfloat162*)(g_Vb + (size_t)c*DIM);
    float acc = 0.f;
    #pragma unroll
    for (int u = 0; u < 4; u++) {
        int p = lane + 32*u;
        if (p < 100) {
            __nv_bfloat162 uv = ur[p], vv = vr[p];
            float h0 = fmaxf(__bfloat162float(uv.x) + __bfloat162float(vv.x), 0.f);
            float h1 = fmaxf(__bfloat162float(uv.y) + __bfloat162float(vv.y), 0.f);
            acc = fmaf(h0, W2[2*p], acc);
            acc = fmaf(h1, W2[2*p+1], acc);
        }
    }
    acc = warp_sum(acc);
    if (lane == 0) new_edge[e] = adj_val[e] * gate_fn(acc + b2[0], eps[e]);
}

// plain CSR SpMM
__global__ void spmm_k(const int* __restrict__ rowptr, const int* __restrict__ col,
                       const float* __restrict__ val, const float* __restrict__ x,
                       float* __restrict__ y) {
    int r = (blockIdx.x*blockDim.x + threadIdx.x) >> 5;
    int lane = threadIdx.x & 31;
    if (r >= NE) return;
    float acc[7];
    #pragma unroll
    for (int u = 0; u < 7; u++) acc[u] = 0.f;
    int s = rowptr[r], e = rowptr[r+1];
    for (int idx = s; idx < e; idx++) {
        int c = __ldg(&col[idx]);
        float v = __ldg(&val[idx]);
        const float* xr = x + (size_t)c*DIM;
        #pragma unroll
        for (int u = 0; u < 7; u++) {
            int j = lane + 32*u;
            if (j < 200) acc[u] = fmaf(v, xr[j], acc[u]);
        }
    }
    float* yr = y + (size_t)r*DIM;
    #pragma unroll
    for (int u = 0; u < 7; u++) {
        int j = lane + 32*u;
        if (j < 200) yr[j] = acc[u];
    }
}

// SpMM + mix fused
template<int WRITE_MP>
__global__ void spmm_mix_k(const int* __restrict__ rowptr, const int* __restrict__ col,
                           const float* __restrict__ val, const float* __restrict__ x,
                           const float* __restrict__ mask,
                           float* __restrict__ y, float* __restrict__ mp_out) {
    int r = (blockIdx.x*blockDim.x + threadIdx.x) >> 5;
    int lane = threadIdx.x & 31;
    if (r >= NE) return;
    float acc[7];
    #pragma unroll
    for (int u = 0; u < 7; u++) acc[u] = 0.f;
    int s = rowptr[r], e = rowptr[r+1];
    for (int idx = s; idx < e; idx++) {
        int c = __ldg(&col[idx]);
        float v = __ldg(&val[idx]);
        const float* xr = x + (size_t)c*DIM;
        #pragma unroll
        for (int u = 0; u < 7; u++) {
            int j = lane + 32*u;
            if (j < 200) acc[u] = fmaf(v, xr[j], acc[u]);
        }
    }
    float m = mask[r];
    const float* xr = x + (size_t)r*DIM;
    float* yr = y + (size_t)r*DIM;
    #pragma unroll
    for (int u = 0; u < 7; u++) {
        int j = lane + 32*u;
        if (j < 200) {
            if (WRITE_MP) mp_out[(size_t)r*DIM + j] = acc[u];
            yr[j] = m*xr[j] + (1.f - m)*acc[u];
        }
    }
}

// RESCAL -> bf16 hrb directly
__global__ void rescal_k(const float* __restrict__ e0, const float* __restrict__ rel_emb,
                         const int* __restrict__ sub, const int* __restrict__ rel) {
    int b = blockIdx.x;
    int j = threadIdx.x;
    __shared__ float ls[DIM];
    const float* lhs = e0 + (size_t)sub[b]*DIM;
    if (j < DIM) ls[j] = lhs[j];
    __syncthreads();
    if (j < DIM) {
        const float* R = rel_emb + (size_t)rel[b]*RELD;
        float acc = 0.f;
        #pragma unroll 4
        for (int k = 0; k < DIM; k++) acc = fmaf(ls[k], R[(size_t)k*DIM + j], acc);
        g_hrb[(size_t)b*KPAD + j] = __float2bfloat16(acc);
    }
}

// ================= launch ==================================================
extern "C" void kernel_launch(void* const* d_in, const int* in_sizes, int n_in,
                              void* d_out, int out_size) {
    const float* e0       = (const float*)d_in[0];
    const float* rel_emb  = (const float*)d_in[1];
    const float* nW1      = (const float*)d_in[2];
    const float* nb1      = (const float*)d_in[3];
    const float* nW2      = (const float*)d_in[4];
    const float* nb2      = (const float*)d_in[5];
    const float* eW1      = (const float*)d_in[6];
    const float* eb1      = (const float*)d_in[7];
    const float* eW2      = (const float*)d_in[8];
    const float* eb2      = (const float*)d_in[9];
    const int*   adj_row  = (const int*)d_in[10];
    const int*   adj_col  = (const int*)d_in[11];
    const float* adj_val  = (const float*)d_in[12];
    const int*   rw_row   = (const int*)d_in[13];
    const int*   rw_col   = (const int*)d_in[14];
    const float* rw_val   = (const float*)d_in[15];
    const float* node_eps = (const float*)d_in[16];
    const float* edge_eps = (const float*)d_in[17];
    const int*   sub      = (const int*)d_in[18];
    const int*   rel      = (const int*)d_in[19];

    int E   = in_sizes[10];
    int Erw = in_sizes[13];

    float* out        = (float*)d_out;
    float* out_scores = out;
    float* out_xnd    = out + (size_t)BATCH*NE;
    float* out_xed    = out_xnd + (size_t)NE*DIM;

    float *X1, *X2, *MP, *NMASK, *NEWEDGE;
    __nv_bfloat16* Hb;
    int *RPA, *RPR;
    cudaGetSymbolAddress((void**)&X1, g_X1);
    cudaGetSymbolAddress((void**)&X2, g_X2);
    cudaGetSymbolAddress((void**)&MP, g_MP);
    cudaGetSymbolAddress((void**)&NMASK, g_NMASK);
    cudaGetSymbolAddress((void**)&NEWEDGE, g_NEWEDGE);
    cudaGetSymbolAddress((void**)&Hb, g_Hb);
    cudaGetSymbolAddress((void**)&RPA, g_rp_adj);
    cudaGetSymbolAddress((void**)&RPR, g_rp_rw);

    static int attr_done = 0;
    if (!attr_done) {
        cudaFuncSetAttribute(mm_e0w_k, cudaFuncAttributeMaxDynamicSharedMemorySize, 65536);
        cudaFuncSetAttribute(scores_mm_k, cudaFuncAttributeMaxDynamicSharedMemorySize, 65536);
        attr_done = 1;
    }

    const int SPB = (NE*32 + 255)/256;
    const int MT  = (NE + 127)/128;      // 391

    rowptr_k<<<(NE+1+255)/256, 256>>>(adj_row, E, RPA);
    rowptr_k<<<(NE+1+255)/256, 256>>>(rw_row, Erw, RPR);
    conv_e0_k<<<(NE*50 + 255)/256, 256>>>(e0);
    dim3 wgrid((DIM*DIM + 255)/256, 4);
    conv_w_k<<<wgrid, 256>>>(nW1, eW1);

    // combined GEMM: H0,H1 (bf16), U,V (bf16)
    dim3 mgrid(MT, 8);
    mm_e0w_k<<<mgrid, 256, 65536>>>(nb1, eb1);

    // gates
    node_gate_k<<<SPB, 256>>>(Hb,                      nW2,       nb2,     node_eps,      NMASK);
    node_gate_k<<<SPB, 256>>>(Hb + (size_t)NE*DIM,     nW2 + DIM, nb2 + 1, node_eps + NE, NMASK + NE);
    edge_gate_k<<<(E*32 + 255)/256, 256>>>(adj_row, adj_col, adj_val,
                                           eW2 + DIM, eb2 + 1, edge_eps + E, NEWEDGE, E);

    // shared first rw-SpMM + node mix (dual write: MP raw + X1 mixed)
    spmm_mix_k<1><<<SPB, 256>>>(RPR, rw_col, rw_val, e0, NMASK, X1, MP);
    // node-drop branch
    spmm_k<<<SPB, 256>>>(RPA, adj_col, adj_val, X1, X2);
    spmm_mix_k<0><<<SPB, 256>>>(RPR, rw_col, rw_val, X2, NMASK + NE, X1, nullptr);
    spmm_k<<<SPB, 256>>>(RPA, adj_col, adj_val, X1, out_xnd);
    // edge-drop branch (reuses MP = rw@e0)
    spmm_k<<<SPB, 256>>>(RPR, rw_col, rw_val, MP, X1);
    spmm_k<<<SPB, 256>>>(RPA, adj_col, NEWEDGE, X1, out_xed);

    // RESCAL (writes bf16 hrb) + scores
    rescal_k<<<BATCH, 256>>>(e0, rel_emb, sub, rel);
    dim3 sgrid(MT, BATCH/128);
    scores_mm_k<<<sgrid, 256, 65536>>>(out_scores);
}

// round 7
// speedup vs baseline: 1.1623x; 1.1623x over previous
#include <cuda_runtime.h>
#include <cuda_bf16.h>
#include <math.h>
#include <stdint.h>

#define NE    50000
#define DIM   200
#define BATCH 1024
#define EMAX  400000
#define RELD  40000
#define KPAD  256          // [data(200) | zero-pad(56)]
#define NCHUNK 4
#define NPAD  256

// ---------------- scratch (zero-init => pad regions stay 0)
__device__ __align__(16) __nv_bfloat16 g_e0b[(size_t)NE*KPAD];
__device__ __align__(16) __nv_bfloat16 g_hrb[(size_t)BATCH*KPAD];
__device__ __align__(16) __nv_bfloat16 g_Wtb[(size_t)4*NPAD*KPAD];
__device__ __align__(4) __nv_bfloat16 g_Ub[(size_t)NE*DIM];
__device__ __align__(4) __nv_bfloat16 g_Vb[(size_t)NE*DIM];
__device__ float g_X1[NE*DIM];
__device__ float g_X2[NE*DIM];
__device__ float g_MP[NE*DIM];
__device__ float g_NMASK[2*NE];
__device__ float g_NEWEDGE[EMAX];
__device__ int   g_rp_adj[NE+1];
__device__ int   g_rp_rw [NE+1];

// ================= helpers =================
__device__ __forceinline__ uint32_t smem_u32(const void* p) {
    uint32_t a;
    asm("{ .reg .u64 t; cvta.to.shared.u64 t, %1; cvt.u32.u64 %0, t; }" : "=r"(a) : "l"(p));
    return a;
}
#define SW128(o) ((o) ^ (((o) >> 3) & 0x70))

__device__ __forceinline__ void ldmx4(uint32_t* r, uint32_t addr) {
    asm volatile("ldmatrix.sync.aligned.m8n8.x4.shared.b16 {%0,%1,%2,%3}, [%4];"
        : "=r"(r[0]), "=r"(r[1]), "=r"(r[2]), "=r"(r[3]) : "r"(addr));
}
__device__ __forceinline__ void mma16816(float* c, const uint32_t* a, const uint32_t* b) {
    asm volatile("mma.sync.aligned.m16n8k16.row.col.f32.bf16.bf16.f32 "
        "{%0,%1,%2,%3}, {%4,%5,%6,%7}, {%8,%9}, {%0,%1,%2,%3};"
        : "+f"(c[0]), "+f"(c[1]), "+f"(c[2]), "+f"(c[3])
        : "r"(a[0]), "r"(a[1]), "r"(a[2]), "r"(a[3]), "r"(b[0]), "r"(b[1]));
}
__device__ __forceinline__ void cpa16(uint32_t dst, const void* src) {
    asm volatile("cp.async.cg.shared.global [%0], [%1], 16;" :: "r"(dst), "l"(src));
}
#define CPA_COMMIT() asm volatile("cp.async.commit_group;" ::: "memory")
#define CPA_WAIT(n)  asm volatile("cp.async.wait_group %0;" :: "n"(n) : "memory")

__device__ __forceinline__ float gate_fn(float logits, float u) {
    const float bias = 1e-4f;
    float eps = (2.f*bias - 1.f)*u + (1.f - bias);
    float t = 2.f*(__logf(eps) - __logf(1.f - eps) + logits);
    return 1.f/(1.f + __expf(-t));
}
__device__ __forceinline__ float warp_sum(float v) {
    #pragma unroll
    for (int o = 16; o; o >>= 1) v += __shfl_xor_sync(0xffffffffu, v, o);
    return v;
}

// ================= conversion kernels =================
__global__ void conv_e0_k(const float* __restrict__ e0) {
    int t = blockIdx.x*blockDim.x + threadIdx.x;
    if (t >= NE*50) return;
    int row = t/50, k = (t%50)*4;
    float4 v = *(const float4*)(e0 + (size_t)row*DIM + k);
    __nv_bfloat162 p0, p1;
    p0.x = __float2bfloat16(v.x); p0.y = __float2bfloat16(v.y);
    p1.x = __float2bfloat16(v.z); p1.y = __float2bfloat16(v.w);
    __nv_bfloat16* d = g_e0b + (size_t)row*KPAD + k;
    *(__nv_bfloat162*)(d)     = p0;
    *(__nv_bfloat162*)(d + 2) = p1;
}

// W (k-major src[k][n]) -> Wt[n][KPAD]
__global__ void conv_w_k(const float* __restrict__ nW1, const float* __restrict__ eW1) {
    int inst = blockIdx.y;
    int t = blockIdx.x*blockDim.x + threadIdx.x;
    if (t >= DIM*DIM) return;
    const float* src;
    if (inst == 0)      src = nW1;
    else if (inst == 1) src = nW1 + RELD;
    else if (inst == 2) src = eW1 + 2*RELD;
    else                src = eW1 + 3*RELD;
    int n = t/DIM, k = t%DIM;
    g_Wtb[(size_t)inst*NPAD*KPAD + (size_t)n*KPAD + k] = __float2bfloat16(src[(size_t)k*DIM + n]);
}

// ================= HMMA machinery (R4: warp tile 32x32) ====================
struct MmaCtx {
    int aAtom0, aAtom1, aLine0, aLine1, aKadd;
    int bAtom0, bAtom1, bLine0, bLine1, bKadd;
};
__device__ __forceinline__ void mma_setup(MmaCtx& cx, int tid) {
    int lane = tid & 31, i = lane >> 3, rr = lane & 7;
    int w = tid >> 5;
    int wm = w >> 1, wn = w & 1;
    int ar0 = wm*32 + (i&1)*8 + rr;
    int ar1 = ar0 + 16;
    int br0 = wn*32 + (i>>1)*8 + rr;
    int br1 = br0 + 16;
    cx.aAtom0 = (ar0>>3)*1024; cx.aLine0 = (ar0&7)*128;
    cx.aAtom1 = (ar1>>3)*1024; cx.aLine1 = (ar1&7)*128;
    cx.aKadd = (i>>1)*16;
    cx.bAtom0 = (br0>>3)*1024; cx.bLine0 = (br0&7)*128;
    cx.bAtom1 = (br1>>3)*1024; cx.bLine1 = (br1&7)*128;
    cx.bKadd = (i&1)*16;
}
__device__ __forceinline__ void mma_chunk(const MmaCtx& cx, uint32_t aA, uint32_t aB,
                                          float acc[2][4][4]) {
    #pragma unroll
    for (int ks = 0; ks < 4; ks++) {
        int kb = ks*32;
        uint32_t a0[4], a1[4], b0[4], b1[4];
        ldmx4(a0, aA + cx.aAtom0 + SW128(cx.aLine0 + kb + cx.aKadd));
        ldmx4(a1, aA + cx.aAtom1 + SW128(cx.aLine1 + kb + cx.aKadd));
        ldmx4(b0, aB + cx.bAtom0 + SW128(cx.bLine0 + kb + cx.bKadd));
        ldmx4(b1, aB + cx.bAtom1 + SW128(cx.bLine1 + kb + cx.bKadd));
        mma16816(acc[0][0], a0, b0);
        mma16816(acc[0][1], a0, b0 + 2);
        mma16816(acc[0][2], a0, b1);
        mma16816(acc[0][3], a0, b1 + 2);
        mma16816(acc[1][0], a1, b0);
        mma16816(acc[1][1], a1, b0 + 2);
        mma16816(acc[1][2], a1, b1);
        mma16816(acc[1][3], a1, b1 + 2);
    }
}
__device__ __forceinline__ void load_a128_async(uint32_t sA, const __nv_bfloat16* Ag,
                                                int row0, int rmax, int c, int tid) {
    #pragma unroll
    for (int i = 0; i < 4; i++) {
        int idx = tid + i*256;
        int r = idx >> 3, q = idx & 7;
        int gr = row0 + r; if (gr >= rmax) gr = 0;
        uint32_t off = (uint32_t)((r>>3)*1024) + SW128((uint32_t)((r&7)*128 + q*16));
        cpa16(sA + off, Ag + (size_t)gr*KPAD + c*64 + q*8);
    }
}
__device__ __forceinline__ void load_b64_async(uint32_t sB, const __nv_bfloat16* Bg,
                                               int row0, int rmax, int c, int tid) {
    #pragma unroll
    for (int i = 0; i < 2; i++) {
        int idx = tid + i*256;
        int r = idx >> 3, q = idx & 7;
        int gr = row0 + r; if (gr >= rmax) gr = 0;
        uint32_t off = (uint32_t)((r>>3)*1024) + SW128((uint32_t)((r&7)*128 + q*16));
        cpa16(sB + off, Bg + (size_t)gr*KPAD + c*64 + q*8);
    }
}

// ================= GEMM 1: C[50000 x 200] = e0 @ W (4 instances) ===========
// inst 0,1 -> H fp32 (X1/X2); inst 2 -> U bf16; inst 3 -> V bf16 (+bias)
__global__ void __launch_bounds__(256) mm_e0w_k(
    const float* __restrict__ nb1, const float* __restrict__ eb1,
    float* __restrict__ H0, float* __restrict__ H1)
{
    __shared__ __align__(1024) uint8_t sA[2][16384];
    __shared__ __align__(1024) uint8_t sB[2][8192];
    int bm = blockIdx.x, nt64 = blockIdx.y, inst = blockIdx.z;
    int tid = threadIdx.x;
    uint32_t aA0 = smem_u32(sA[0]), aA1 = smem_u32(sA[1]);
    uint32_t aB0 = smem_u32(sB[0]), aB1 = smem_u32(sB[1]);

    MmaCtx cx; mma_setup(cx, tid);
    float acc[2][4][4];
    #pragma unroll
    for (int a = 0; a < 2; a++)
        #pragma unroll
        for (int b = 0; b < 4; b++)
            #pragma unroll
            for (int q = 0; q < 4; q++) acc[a][b][q] = 0.f;

    const __nv_bfloat16* Bg = g_Wtb + (size_t)inst*NPAD*KPAD;

    load_a128_async(aA0, g_e0b, bm*128, NE, 0, tid);
    load_b64_async (aB0, Bg, nt64*64, NPAD, 0, tid);
    CPA_COMMIT();
    #pragma unroll
    for (int c = 0; c < NCHUNK; c++) {
        uint32_t curA = (c & 1) ? aA1 : aA0, curB = (c & 1) ? aB1 : aB0;
        if (c + 1 < NCHUNK) {
            uint32_t nxtA = ((c+1) & 1) ? aA1 : aA0, nxtB = ((c+1) & 1) ? aB1 : aB0;
            load_a128_async(nxtA, g_e0b, bm*128, NE, c+1, tid);
            load_b64_async (nxtB, Bg, nt64*64, NPAD, c+1, tid);
            CPA_COMMIT();
            CPA_WAIT(1);
        } else {
            CPA_WAIT(0);
        }
        __syncthreads();
        mma_chunk(cx, curA, curB, acc);
        __syncthreads();
    }

    int lane = tid & 31, w = tid >> 5;
    int wm = w >> 1, wn = w & 1;
    int mrow = lane >> 2, ncol = (lane & 3)*2;

    if (inst < 2) {
        float* C = (inst == 0) ? H0 : H1;
        const float* bias = nb1 + inst*DIM;
        #pragma unroll
        for (int mt = 0; mt < 2; mt++) {
            int m = bm*128 + wm*32 + mt*16 + mrow;
            if (m >= NE) continue;
            #pragma unroll
            for (int nt = 0; nt < 4; nt++) {
                int n = nt64*64 + wn*32 + nt*8 + ncol;
                if (n >= DIM) continue;
                float b0 = bias[n], b1 = bias[n+1];
                float2 v01, v23;
                v01.x = fmaxf(acc[mt][nt][0] + b0, 0.f);
                v01.y = fmaxf(acc[mt][nt][1] + b1, 0.f);
                v23.x = fmaxf(acc[mt][nt][2] + b0, 0.f);
                v23.y = fmaxf(acc[mt][nt][3] + b1, 0.f);
                *(float2*)(C + (size_t)m*DIM + n) = v01;
                if (m + 8 < NE) *(float2*)(C + (size_t)(m+8)*DIM + n) = v23;
            }
        }
    } else {
        __nv_bfloat16* C = (inst == 2) ? g_Ub : g_Vb;
        const float* bias = (inst == 3) ? (eb1 + DIM) : nullptr;
        #pragma unroll
        for (int mt = 0; mt < 2; mt++) {
            int m = bm*128 + wm*32 + mt*16 + mrow;
            if (m >= NE) continue;
            #pragma unroll
            for (int nt = 0; nt < 4; nt++) {
                int n = nt64*64 + wn*32 + nt*8 + ncol;
                if (n >= DIM) continue;
                float b0 = bias ? bias[n] : 0.f, b1 = bias ? bias[n+1] : 0.f;
                __nv_bfloat162 p, q;
                p.x = __float2bfloat16(acc[mt][nt][0] + b0);
                p.y = __float2bfloat16(acc[mt][nt][1] + b1);
                q.x = __float2bfloat16(acc[mt][nt][2] + b0);
                q.y = __float2bfloat16(acc[mt][nt][3] + b1);
                *(__nv_bfloat162*)(C + (size_t)m*DIM + n) = p;
                if (m + 8 < NE) *(__nv_bfloat162*)(C + (size_t)(m+8)*DIM + n) = q;
            }
        }
    }
}

// ================= GEMM 2: scores = sigmoid(HR @ E0^T), R4 geometry ========
__global__ void __launch_bounds__(256) scores_mm_k(float* __restrict__ out)
{
    __shared__ __align__(1024) uint8_t sA[2][16384];
    __shared__ __align__(1024) uint8_t sB[2][8192];
    int bx = blockIdx.x, by = blockIdx.y;
    int tid = threadIdx.x;
    uint32_t aA0 = smem_u32(sA[0]), aA1 = smem_u32(sA[1]);
    uint32_t aB0 = smem_u32(sB[0]), aB1 = smem_u32(sB[1]);

    MmaCtx cx; mma_setup(cx, tid);
    float acc[2][4][4];
    #pragma unroll
    for (int a = 0; a < 2; a++)
        #pragma unroll
        for (int b = 0; b < 4; b++)
            #pragma unroll
            for (int q = 0; q < 4; q++) acc[a][b][q] = 0.f;

    load_a128_async(aA0, g_hrb, by*128, BATCH, 0, tid);
    load_b64_async (aB0, g_e0b, bx*64, NE, 0, tid);
    CPA_COMMIT();
    #pragma unroll
    for (int c = 0; c < NCHUNK; c++) {
        uint32_t curA = (c & 1) ? aA1 : aA0, curB = (c & 1) ? aB1 : aB0;
        if (c + 1 < NCHUNK) {
            uint32_t nxtA = ((c+1) & 1) ? aA1 : aA0, nxtB = ((c+1) & 1) ? aB1 : aB0;
            load_a128_async(nxtA, g_hrb, by*128, BATCH, c+1, tid);
            load_b64_async (nxtB, g_e0b, bx*64, NE, c+1, tid);
            CPA_COMMIT();
            CPA_WAIT(1);
        } else {
            CPA_WAIT(0);
        }
        __syncthreads();
        mma_chunk(cx, curA, curB, acc);
        __syncthreads();
    }

    int lane = tid & 31, w = tid >> 5;
    int wm = w >> 1, wn = w & 1;
    int mrow = lane >> 2, ncol = (lane & 3)*2;
    #pragma unroll
    for (int mt = 0; mt < 2; mt++) {
        int m = by*128 + wm*32 + mt*16 + mrow;
        #pragma unroll
        for (int nt = 0; nt < 4; nt++) {
            int n = bx*64 + wn*32 + nt*8 + ncol;
            if (n < NE) {
                float2 v01, v23;
                v01.x = 1.f/(1.f + __expf(-acc[mt][nt][0]));
                v01.y = 1.f/(1.f + __expf(-acc[mt][nt][1]));
                v23.x = 1.f/(1.f + __expf(-acc[mt][nt][2]));
                v23.y = 1.f/(1.f + __expf(-acc[mt][nt][3]));
                *(float2*)(out + (size_t)m*NE + n) = v01;
                *(float2*)(out + (size_t)(m+8)*NE + n) = v23;
            }
        }
    }
}

// ================= support kernels =================
__global__ void rowptr_k(const int* __restrict__ row, int nnz, int* __restrict__ rowptr) {
    int n = blockIdx.x*blockDim.x + threadIdx.x;
    if (n > NE) return;
    int lo = 0, hi = nnz;
    while (lo < hi) { int mid = (lo+hi) >> 1; if (row[mid] < n) lo = mid+1; else hi = mid; }
    rowptr[n] = lo;
}

__global__ void node_gate_k(const float* __restrict__ H, const float* __restrict__ W2,
                            const float* __restrict__ b2, const float* __restrict__ eps,
                            float* __restrict__ mask) {
    int w = (blockIdx.x*blockDim.x + threadIdx.x) >> 5;
    int lane = threadIdx.x & 31;
    if (w >= NE) return;
    float acc = 0.f;
    const float* hr = H + (size_t)w*DIM;
    #pragma unroll
    for (int u = 0; u < 7; u++) {
        int j = lane + 32*u;
        if (j < 200) acc = fmaf(hr[j], W2[j], acc);
    }
    acc = warp_sum(acc);
    if (lane == 0) mask[w] = gate_fn(acc + b2[0], eps[w]);
}

// edge gate from bf16 U/V
__global__ void edge_gate_k(const int* __restrict__ row, const int* __restrict__ col,
                            const float* __restrict__ adj_val,
                            const float* __restrict__ W2, const float* __restrict__ b2,
                            const float* __restrict__ eps, float* __restrict__ new_edge,
                            int E) {
    int e = (blockIdx.x*blockDim.x + threadIdx.x) >> 5;
    int lane = threadIdx.x & 31;
    if (e >= E) return;
    int r = row[e], c = col[e];
    const __nv_bfloat162* ur = (const __nv_bfloat162*)(g_Ub + (size_t)r*DIM);
    const __nv_bfloat162* vr = (const __nv_bfloat162*)(g_Vb + (size_t)c*DIM);
    float acc = 0.f;
    #pragma unroll
    for (int u = 0; u < 4; u++) {
        int p = lane + 32*u;
        if (p < 100) {
            __nv_bfloat162 uv = ur[p], vv = vr[p];
            float h0 = fmaxf(__bfloat162float(uv.x) + __bfloat162float(vv.x), 0.f);
            float h1 = fmaxf(__bfloat162float(uv.y) + __bfloat162float(vv.y), 0.f);
            acc = fmaf(h0, W2[2*p], acc);
            acc = fmaf(h1, W2[2*p+1], acc);
        }
    }
    acc = warp_sum(acc);
    if (lane == 0) new_edge[e] = adj_val[e] * gate_fn(acc + b2[0], eps[e]);
}

// plain CSR SpMM
__global__ void spmm_k(const int* __restrict__ rowptr, const int* __restrict__ col,
                       const float* __restrict__ val, const float* __restrict__ x,
                       float* __restrict__ y) {
    int r = (blockIdx.x*blockDim.x + threadIdx.x) >> 5;
    int lane = threadIdx.x & 31;
    if (r >= NE) return;
    float acc[7];
    #pragma unroll
    for (int u = 0; u < 7; u++) acc[u] = 0.f;
    int s = rowptr[r], e = rowptr[r+1];
    for (int idx = s; idx < e; idx++) {
        int c = __ldg(&col[idx]);
        float v = __ldg(&val[idx]);
        const float* xr = x + (size_t)c*DIM;
        #pragma unroll
        for (int u = 0; u < 7; u++) {
            int j = lane + 32*u;
            if (j < 200) acc[u] = fmaf(v, xr[j], acc[u]);
        }
    }
    float* yr = y + (size_t)r*DIM;
    #pragma unroll
    for (int u = 0; u < 7; u++) {
        int j = lane + 32*u;
        if (j < 200) yr[j] = acc[u];
    }
}

// SpMM + mix fused
template<int WRITE_MP>
__global__ void spmm_mix_k(const int* __restrict__ rowptr, const int* __restrict__ col,
                           const float* __restrict__ val, const float* __restrict__ x,
                           const float* __restrict__ mask,
                           float* __restrict__ y, float* __restrict__ mp_out) {
    int r = (blockIdx.x*blockDim.x + threadIdx.x) >> 5;
    int lane = threadIdx.x & 31;
    if (r >= NE) return;
    float acc[7];
    #pragma unroll
    for (int u = 0; u < 7; u++) acc[u] = 0.f;
    int s = rowptr[r], e = rowptr[r+1];
    for (int idx = s; idx < e; idx++) {
        int c = __ldg(&col[idx]);
        float v = __ldg(&val[idx]);
        const float* xr = x + (size_t)c*DIM;
        #pragma unroll
        for (int u = 0; u < 7; u++) {
            int j = lane + 32*u;
            if (j < 200) acc[u] = fmaf(v, xr[j], acc[u]);
        }
    }
    float m = mask[r];
    const float* xr = x + (size_t)r*DIM;
    float* yr = y + (size_t)r*DIM;
    #pragma unroll
    for (int u = 0; u < 7; u++) {
        int j = lane + 32*u;
        if (j < 200) {
            if (WRITE_MP) mp_out[(size_t)r*DIM + j] = acc[u];
            yr[j] = m*xr[j] + (1.f - m)*acc[u];
        }
    }
}

// RESCAL -> bf16 hrb directly
__global__ void rescal_k(const float* __restrict__ e0, const float* __restrict__ rel_emb,
                         const int* __restrict__ sub, const int* __restrict__ rel) {
    int b = blockIdx.x;
    int j = threadIdx.x;
    __shared__ float ls[DIM];
    const float* lhs = e0 + (size_t)sub[b]*DIM;
    if (j < DIM) ls[j] = lhs[j];
    __syncthreads();
    if (j < DIM) {
        const float* R = rel_emb + (size_t)rel[b]*RELD;
        float acc = 0.f;
        #pragma unroll 4
        for (int k = 0; k < DIM; k++) acc = fmaf(ls[k], R[(size_t)k*DIM + j], acc);
        g_hrb[(size_t)b*KPAD + j] = __float2bfloat16(acc);
    }
}

// ================= launch ==================================================
extern "C" void kernel_launch(void* const* d_in, const int* in_sizes, int n_in,
                              void* d_out, int out_size) {
    const float* e0       = (const float*)d_in[0];
    const float* rel_emb  = (const float*)d_in[1];
    const float* nW1      = (const float*)d_in[2];
    const float* nb1      = (const float*)d_in[3];
    const float* nW2      = (const float*)d_in[4];
    const float* nb2      = (const float*)d_in[5];
    const float* eW1      = (const float*)d_in[6];
    const float* eb1      = (const float*)d_in[7];
    const float* eW2      = (const float*)d_in[8];
    const float* eb2      = (const float*)d_in[9];
    const int*   adj_row  = (const int*)d_in[10];
    const int*   adj_col  = (const int*)d_in[11];
    const float* adj_val  = (const float*)d_in[12];
    const int*   rw_row   = (const int*)d_in[13];
    const int*   rw_col   = (const int*)d_in[14];
    const float* rw_val   = (const float*)d_in[15];
    const float* node_eps = (const float*)d_in[16];
    const float* edge_eps = (const float*)d_in[17];
    const int*   sub      = (const int*)d_in[18];
    const int*   rel      = (const int*)d_in[19];

    int E   = in_sizes[10];
    int Erw = in_sizes[13];

    float* out        = (float*)d_out;
    float* out_scores = out;
    float* out_xnd    = out + (size_t)BATCH*NE;
    float* out_xed    = out_xnd + (size_t)NE*DIM;

    float *X1, *X2, *MP, *NMASK, *NEWEDGE;
    int *RPA, *RPR;
    cudaGetSymbolAddress((void**)&X1, g_X1);
    cudaGetSymbolAddress((void**)&X2, g_X2);
    cudaGetSymbolAddress((void**)&MP, g_MP);
    cudaGetSymbolAddress((void**)&NMASK, g_NMASK);
    cudaGetSymbolAddress((void**)&NEWEDGE, g_NEWEDGE);
    cudaGetSymbolAddress((void**)&RPA, g_rp_adj);
    cudaGetSymbolAddress((void**)&RPR, g_rp_rw);

    const int SPB = (NE*32 + 255)/256;
    const int MT  = (NE + 127)/128;      // 391

    rowptr_k<<<(NE+1+255)/256, 256>>>(adj_row, E, RPA);
    rowptr_k<<<(NE+1+255)/256, 256>>>(rw_row, Erw, RPR);
    conv_e0_k<<<(NE*50 + 255)/256, 256>>>(e0);
    dim3 wgrid((DIM*DIM + 255)/256, 4);
    conv_w_k<<<wgrid, 256>>>(nW1, eW1);

    // HMMA GEMM: H0 (X1 fp32), H1 (X2 fp32), U (bf16), V (bf16)
    dim3 mgrid(MT, 4, 4);
    mm_e0w_k<<<mgrid, 256>>>(nb1, eb1, X1, X2);

    // gates
    node_gate_k<<<SPB, 256>>>(X1, nW2,       nb2,     node_eps,      NMASK);
    node_gate_k<<<SPB, 256>>>(X2, nW2 + DIM, nb2 + 1, node_eps + NE, NMASK + NE);
    edge_gate_k<<<(E*32 + 255)/256, 256>>>(adj_row, adj_col, adj_val,
                                           eW2 + DIM, eb2 + 1, edge_eps + E, NEWEDGE, E);

    // shared first rw-SpMM + node mix (dual write: MP raw + X1 mixed)
    spmm_mix_k<1><<<SPB, 256>>>(RPR, rw_col, rw_val, e0, NMASK, X1, MP);
    // node-drop branch
    spmm_k<<<SPB, 256>>>(RPA, adj_col, adj_val, X1, X2);
    spmm_mix_k<0><<<SPB, 256>>>(RPR, rw_col, rw_val, X2, NMASK + NE, X1, nullptr);
    spmm_k<<<SPB, 256>>>(RPA, adj_col, adj_val, X1, out_xnd);
    // edge-drop branch (reuses MP = rw@e0)
    spmm_k<<<SPB, 256>>>(RPR, rw_col, rw_val, MP, X1);
    spmm_k<<<SPB, 256>>>(RPA, adj_col, NEWEDGE, X1, out_xed);

    // RESCAL (writes bf16 hrb) + scores (R4 geometry)
    rescal_k<<<BATCH, 256>>>(e0, rel_emb, sub, rel);
    dim3 sgrid((NE + 63)/64, BATCH/128);
    scores_mm_k<<<sgrid, 256>>>(out_scores);
}

// round 8
// speedup vs baseline: 1.2225x; 1.0518x over previous
#include <cuda_runtime.h>
#include <cuda_bf16.h>
#include <math.h>
#include <stdint.h>

#define NE    50000
#define DIM   200
#define BATCH 1024
#define EMAX  400000
#define RELD  40000
#define KPAD  256
#define NCHUNK 4
#define NPAD  256

// ---------------- scratch (zero-init => pad regions stay 0)
__device__ __align__(16) __nv_bfloat16 g_e0b[(size_t)NE*KPAD];
__device__ __align__(16) __nv_bfloat16 g_hrb[(size_t)BATCH*KPAD];
__device__ __align__(16) __nv_bfloat16 g_Wtb[(size_t)4*NPAD*KPAD];
__device__ __align__(4) __nv_bfloat16 g_Ub[(size_t)NE*DIM];
__device__ __align__(4) __nv_bfloat16 g_Vb[(size_t)NE*DIM];
__device__ float g_X1[NE*DIM];
__device__ float g_X2[NE*DIM];
__device__ float g_MP[NE*DIM];
__device__ float g_E2[NE*DIM];
__device__ float g_NMASK[2*NE];
__device__ float g_NEWEDGE[EMAX];
__device__ int   g_rp_adj[NE+1];
__device__ int   g_rp_rw [NE+1];

// ================= helpers =================
__device__ __forceinline__ uint32_t smem_u32(const void* p) {
    uint32_t a;
    asm("{ .reg .u64 t; cvta.to.shared.u64 t, %1; cvt.u32.u64 %0, t; }" : "=r"(a) : "l"(p));
    return a;
}
#define SW128(o) ((o) ^ (((o) >> 3) & 0x70))

__device__ __forceinline__ void ldmx4(uint32_t* r, uint32_t addr) {
    asm volatile("ldmatrix.sync.aligned.m8n8.x4.shared.b16 {%0,%1,%2,%3}, [%4];"
        : "=r"(r[0]), "=r"(r[1]), "=r"(r[2]), "=r"(r[3]) : "r"(addr));
}
__device__ __forceinline__ void mma16816(float* c, const uint32_t* a, const uint32_t* b) {
    asm volatile("mma.sync.aligned.m16n8k16.row.col.f32.bf16.bf16.f32 "
        "{%0,%1,%2,%3}, {%4,%5,%6,%7}, {%8,%9}, {%0,%1,%2,%3};"
        : "+f"(c[0]), "+f"(c[1]), "+f"(c[2]), "+f"(c[3])
        : "r"(a[0]), "r"(a[1]), "r"(a[2]), "r"(a[3]), "r"(b[0]), "r"(b[1]));
}
__device__ __forceinline__ void cpa16(uint32_t dst, const void* src) {
    asm volatile("cp.async.cg.shared.global [%0], [%1], 16;" :: "r"(dst), "l"(src));
}
#define CPA_COMMIT() asm volatile("cp.async.commit_group;" ::: "memory")
#define CPA_WAIT(n)  asm volatile("cp.async.wait_group %0;" :: "n"(n) : "memory")

__device__ __forceinline__ float gate_fn(float logits, float u) {
    const float bias = 1e-4f;
    float eps = (2.f*bias - 1.f)*u + (1.f - bias);
    float t = 2.f*(__logf(eps) - __logf(1.f - eps) + logits);
    return 1.f/(1.f + __expf(-t));
}
__device__ __forceinline__ float warp_sum(float v) {
    #pragma unroll
    for (int o = 16; o; o >>= 1) v += __shfl_xor_sync(0xffffffffu, v, o);
    return v;
}

// ================= conversion kernels =================
__global__ void conv_e0_k(const float* __restrict__ e0) {
    int t = blockIdx.x*blockDim.x + threadIdx.x;
    if (t >= NE*50) return;
    int row = t/50, k = (t%50)*4;
    float4 v = *(const float4*)(e0 + (size_t)row*DIM + k);
    __nv_bfloat162 p0, p1;
    p0.x = __float2bfloat16(v.x); p0.y = __float2bfloat16(v.y);
    p1.x = __float2bfloat16(v.z); p1.y = __float2bfloat16(v.w);
    __nv_bfloat16* d = g_e0b + (size_t)row*KPAD + k;
    *(__nv_bfloat162*)(d)     = p0;
    *(__nv_bfloat162*)(d + 2) = p1;
}

__global__ void conv_w_k(const float* __restrict__ nW1, const float* __restrict__ eW1) {
    int inst = blockIdx.y;
    int t = blockIdx.x*blockDim.x + threadIdx.x;
    if (t >= DIM*DIM) return;
    const float* src;
    if (inst == 0)      src = nW1;
    else if (inst == 1) src = nW1 + RELD;
    else if (inst == 2) src = eW1 + 2*RELD;
    else                src = eW1 + 3*RELD;
    int n = t/DIM, k = t%DIM;
    g_Wtb[(size_t)inst*NPAD*KPAD + (size_t)n*KPAD + k] = __float2bfloat16(src[(size_t)k*DIM + n]);
}

// ================= HMMA machinery (R4 geometry) ============================
struct MmaCtx {
    int aAtom0, aAtom1, aLine0, aLine1, aKadd;
    int bAtom0, bAtom1, bLine0, bLine1, bKadd;
};
__device__ __forceinline__ void mma_setup(MmaCtx& cx, int tid) {
    int lane = tid & 31, i = lane >> 3, rr = lane & 7;
    int w = tid >> 5;
    int wm = w >> 1, wn = w & 1;
    int ar0 = wm*32 + (i&1)*8 + rr;
    int ar1 = ar0 + 16;
    int br0 = wn*32 + (i>>1)*8 + rr;
    int br1 = br0 + 16;
    cx.aAtom0 = (ar0>>3)*1024; cx.aLine0 = (ar0&7)*128;
    cx.aAtom1 = (ar1>>3)*1024; cx.aLine1 = (ar1&7)*128;
    cx.aKadd = (i>>1)*16;
    cx.bAtom0 = (br0>>3)*1024; cx.bLine0 = (br0&7)*128;
    cx.bAtom1 = (br1>>3)*1024; cx.bLine1 = (br1&7)*128;
    cx.bKadd = (i&1)*16;
}
__device__ __forceinline__ void mma_chunk(const MmaCtx& cx, uint32_t aA, uint32_t aB,
                                          float acc[2][4][4]) {
    #pragma unroll
    for (int ks = 0; ks < 4; ks++) {
        int kb = ks*32;
        uint32_t a0[4], a1[4], b0[4], b1[4];
        ldmx4(a0, aA + cx.aAtom0 + SW128(cx.aLine0 + kb + cx.aKadd));
        ldmx4(a1, aA + cx.aAtom1 + SW128(cx.aLine1 + kb + cx.aKadd));
        ldmx4(b0, aB + cx.bAtom0 + SW128(cx.bLine0 + kb + cx.bKadd));
        ldmx4(b1, aB + cx.bAtom1 + SW128(cx.bLine1 + kb + cx.bKadd));
        mma16816(acc[0][0], a0, b0);
        mma16816(acc[0][1], a0, b0 + 2);
        mma16816(acc[0][2], a0, b1);
        mma16816(acc[0][3], a0, b1 + 2);
        mma16816(acc[1][0], a1, b0);
        mma16816(acc[1][1], a1, b0 + 2);
        mma16816(acc[1][2], a1, b1);
        mma16816(acc[1][3], a1, b1 + 2);
    }
}
__device__ __forceinline__ void load_a128_async(uint32_t sA, const __nv_bfloat16* Ag,
                                                int row0, int rmax, int c, int tid) {
    #pragma unroll
    for (int i = 0; i < 4; i++) {
        int idx = tid + i*256;
        int r = idx >> 3, q = idx & 7;
        int gr = row0 + r; if (gr >= rmax) gr = 0;
        uint32_t off = (uint32_t)((r>>3)*1024) + SW128((uint32_t)((r&7)*128 + q*16));
        cpa16(sA + off, Ag + (size_t)gr*KPAD + c*64 + q*8);
    }
}
__device__ __forceinline__ void load_b64_async(uint32_t sB, const __nv_bfloat16* Bg,
                                               int row0, int rmax, int c, int tid) {
    #pragma unroll
    for (int i = 0; i < 2; i++) {
        int idx = tid + i*256;
        int r = idx >> 3, q = idx & 7;
        int gr = row0 + r; if (gr >= rmax) gr = 0;
        uint32_t off = (uint32_t)((r>>3)*1024) + SW128((uint32_t)((r&7)*128 + q*16));
        cpa16(sB + off, Bg + (size_t)gr*KPAD + c*64 + q*8);
    }
}

// ================= GEMM 1: e0 @ W (4 instances) ============================
__global__ void __launch_bounds__(256) mm_e0w_k(
    const float* __restrict__ nb1, const float* __restrict__ eb1,
    float* __restrict__ H0, float* __restrict__ H1)
{
    __shared__ __align__(1024) uint8_t sA[2][16384];
    __shared__ __align__(1024) uint8_t sB[2][8192];
    int bm = blockIdx.x, nt64 = blockIdx.y, inst = blockIdx.z;
    int tid = threadIdx.x;
    uint32_t aA0 = smem_u32(sA[0]), aA1 = smem_u32(sA[1]);
    uint32_t aB0 = smem_u32(sB[0]), aB1 = smem_u32(sB[1]);

    MmaCtx cx; mma_setup(cx, tid);
    float acc[2][4][4];
    #pragma unroll
    for (int a = 0; a < 2; a++)
        #pragma unroll
        for (int b = 0; b < 4; b++)
            #pragma unroll
            for (int q = 0; q < 4; q++) acc[a][b][q] = 0.f;

    const __nv_bfloat16* Bg = g_Wtb + (size_t)inst*NPAD*KPAD;

    load_a128_async(aA0, g_e0b, bm*128, NE, 0, tid);
    load_b64_async (aB0, Bg, nt64*64, NPAD, 0, tid);
    CPA_COMMIT();
    #pragma unroll
    for (int c = 0; c < NCHUNK; c++) {
        uint32_t curA = (c & 1) ? aA1 : aA0, curB = (c & 1) ? aB1 : aB0;
        if (c + 1 < NCHUNK) {
            uint32_t nxtA = ((c+1) & 1) ? aA1 : aA0, nxtB = ((c+1) & 1) ? aB1 : aB0;
            load_a128_async(nxtA, g_e0b, bm*128, NE, c+1, tid);
            load_b64_async (nxtB, Bg, nt64*64, NPAD, c+1, tid);
            CPA_COMMIT();
            CPA_WAIT(1);
        } else {
            CPA_WAIT(0);
        }
        __syncthreads();
        mma_chunk(cx, curA, curB, acc);
        __syncthreads();
    }

    int lane = tid & 31, w = tid >> 5;
    int wm = w >> 1, wn = w & 1;
    int mrow = lane >> 2, ncol = (lane & 3)*2;

    if (inst < 2) {
        float* C = (inst == 0) ? H0 : H1;
        const float* bias = nb1 + inst*DIM;
        #pragma unroll
        for (int mt = 0; mt < 2; mt++) {
            int m = bm*128 + wm*32 + mt*16 + mrow;
            if (m >= NE) continue;
            #pragma unroll
            for (int nt = 0; nt < 4; nt++) {
                int n = nt64*64 + wn*32 + nt*8 + ncol;
                if (n >= DIM) continue;
                float b0 = bias[n], b1 = bias[n+1];
                float2 v01, v23;
                v01.x = fmaxf(acc[mt][nt][0] + b0, 0.f);
                v01.y = fmaxf(acc[mt][nt][1] + b1, 0.f);
                v23.x = fmaxf(acc[mt][nt][2] + b0, 0.f);
                v23.y = fmaxf(acc[mt][nt][3] + b1, 0.f);
                *(float2*)(C + (size_t)m*DIM + n) = v01;
                if (m + 8 < NE) *(float2*)(C + (size_t)(m+8)*DIM + n) = v23;
            }
        }
    } else {
        __nv_bfloat16* C = (inst == 2) ? g_Ub : g_Vb;
        const float* bias = (inst == 3) ? (eb1 + DIM) : nullptr;
        #pragma unroll
        for (int mt = 0; mt < 2; mt++) {
            int m = bm*128 + wm*32 + mt*16 + mrow;
            if (m >= NE) continue;
            #pragma unroll
            for (int nt = 0; nt < 4; nt++) {
                int n = nt64*64 + wn*32 + nt*8 + ncol;
                if (n >= DIM) continue;
                float b0 = bias ? bias[n] : 0.f, b1 = bias ? bias[n+1] : 0.f;
                __nv_bfloat162 p, q;
                p.x = __float2bfloat16(acc[mt][nt][0] + b0);
                p.y = __float2bfloat16(acc[mt][nt][1] + b1);
                q.x = __float2bfloat16(acc[mt][nt][2] + b0);
                q.y = __float2bfloat16(acc[mt][nt][3] + b1);
                *(__nv_bfloat162*)(C + (size_t)m*DIM + n) = p;
                if (m + 8 < NE) *(__nv_bfloat162*)(C + (size_t)(m+8)*DIM + n) = q;
            }
        }
    }
}

// ================= GEMM 2: scores ==========================================
__global__ void __launch_bounds__(256) scores_mm_k(float* __restrict__ out)
{
    __shared__ __align__(1024) uint8_t sA[2][16384];
    __shared__ __align__(1024) uint8_t sB[2][8192];
    int bx = blockIdx.x, by = blockIdx.y;
    int tid = threadIdx.x;
    uint32_t aA0 = smem_u32(sA[0]), aA1 = smem_u32(sA[1]);
    uint32_t aB0 = smem_u32(sB[0]), aB1 = smem_u32(sB[1]);

    MmaCtx cx; mma_setup(cx, tid);
    float acc[2][4][4];
    #pragma unroll
    for (int a = 0; a < 2; a++)
        #pragma unroll
        for (int b = 0; b < 4; b++)
            #pragma unroll
            for (int q = 0; q < 4; q++) acc[a][b][q] = 0.f;

    load_a128_async(aA0, g_hrb, by*128, BATCH, 0, tid);
    load_b64_async (aB0, g_e0b, bx*64, NE, 0, tid);
    CPA_COMMIT();
    #pragma unroll
    for (int c = 0; c < NCHUNK; c++) {
        uint32_t curA = (c & 1) ? aA1 : aA0, curB = (c & 1) ? aB1 : aB0;
        if (c + 1 < NCHUNK) {
            uint32_t nxtA = ((c+1) & 1) ? aA1 : aA0, nxtB = ((c+1) & 1) ? aB1 : aB0;
            load_a128_async(nxtA, g_hrb, by*128, BATCH, c+1, tid);
            load_b64_async (nxtB, g_e0b, bx*64, NE, c+1, tid);
            CPA_COMMIT();
            CPA_WAIT(1);
        } else {
            CPA_WAIT(0);
        }
        __syncthreads();
        mma_chunk(cx, curA, curB, acc);
        __syncthreads();
    }

    int lane = tid & 31, w = tid >> 5;
    int wm = w >> 1, wn = w & 1;
    int mrow = lane >> 2, ncol = (lane & 3)*2;
    #pragma unroll
    for (int mt = 0; mt < 2; mt++) {
        int m = by*128 + wm*32 + mt*16 + mrow;
        #pragma unroll
        for (int nt = 0; nt < 4; nt++) {
            int n = bx*64 + wn*32 + nt*8 + ncol;
            if (n < NE) {
                float2 v01, v23;
                v01.x = 1.f/(1.f + __expf(-acc[mt][nt][0]));
                v01.y = 1.f/(1.f + __expf(-acc[mt][nt][1]));
                v23.x = 1.f/(1.f + __expf(-acc[mt][nt][2]));
                v23.y = 1.f/(1.f + __expf(-acc[mt][nt][3]));
                *(float2*)(out + (size_t)m*NE + n) = v01;
                *(float2*)(out + (size_t)(m+8)*NE + n) = v23;
            }
        }
    }
}

// ================= support kernels =================
__global__ void rowptr_k(const int* __restrict__ row, int nnz, int* __restrict__ rowptr) {
    int n = blockIdx.x*blockDim.x + threadIdx.x;
    if (n > NE) return;
    int lo = 0, hi = nnz;
    while (lo < hi) { int mid = (lo+hi) >> 1; if (row[mid] < n) lo = mid+1; else hi = mid; }
    rowptr[n] = lo;
}

__global__ void node_gate_k(const float* __restrict__ H, const float* __restrict__ W2,
                            const float* __restrict__ b2, const float* __restrict__ eps,
                            float* __restrict__ mask) {
    int w = (blockIdx.x*blockDim.x + threadIdx.x) >> 5;
    int lane = threadIdx.x & 31;
    if (w >= NE) return;
    float acc = 0.f;
    const float* hr = H + (size_t)w*DIM;
    #pragma unroll
    for (int u = 0; u < 7; u++) {
        int j = lane + 32*u;
        if (j < 200) acc = fmaf(hr[j], W2[j], acc);
    }
    acc = warp_sum(acc);
    if (lane == 0) mask[w] = gate_fn(acc + b2[0], eps[w]);
}

__global__ void edge_gate_k(const int* __restrict__ row, const int* __restrict__ col,
                            const float* __restrict__ adj_val,
                            const float* __restrict__ W2, const float* __restrict__ b2,
                            const float* __restrict__ eps, float* __restrict__ new_edge,
                            int E) {
    int e = (blockIdx.x*blockDim.x + threadIdx.x) >> 5;
    int lane = threadIdx.x & 31;
    if (e >= E) return;
    int r = row[e], c = col[e];
    const __nv_bfloat162* ur = (const __nv_bfloat162*)(g_Ub + (size_t)r*DIM);
    const __nv_bfloat162* vr = (const __nv_bfloat162*)(g_Vb + (size_t)c*DIM);
    float acc = 0.f;
    #pragma unroll
    for (int u = 0; u < 4; u++) {
        int p = lane + 32*u;
        if (p < 100) {
            __nv_bfloat162 uv = ur[p], vv = vr[p];
            float h0 = fmaxf(__bfloat162float(uv.x) + __bfloat162float(vv.x), 0.f);
            float h1 = fmaxf(__bfloat162float(uv.y) + __bfloat162float(vv.y), 0.f);
            acc = fmaf(h0, W2[2*p], acc);
            acc = fmaf(h1, W2[2*p+1], acc);
        }
    }
    acc = warp_sum(acc);
    if (lane == 0) new_edge[e] = adj_val[e] * gate_fn(acc + b2[0], eps[e]);
}

__global__ void spmm_k(const int* __restrict__ rowptr, const int* __restrict__ col,
                       const float* __restrict__ val, const float* __restrict__ x,
                       float* __restrict__ y) {
    int r = (blockIdx.x*blockDim.x + threadIdx.x) >> 5;
    int lane = threadIdx.x & 31;
    if (r >= NE) return;
    float acc[7];
    #pragma unroll
    for (int u = 0; u < 7; u++) acc[u] = 0.f;
    int s = rowptr[r], e = rowptr[r+1];
    for (int idx = s; idx < e; idx++) {
        int c = __ldg(&col[idx]);
        float v = __ldg(&val[idx]);
        const float* xr = x + (size_t)c*DIM;
        #pragma unroll
        for (int u = 0; u < 7; u++) {
            int j = lane + 32*u;
            if (j < 200) acc[u] = fmaf(v, xr[j], acc[u]);
        }
    }
    float* yr = y + (size_t)r*DIM;
    #pragma unroll
    for (int u = 0; u < 7; u++) {
        int j = lane + 32*u;
        if (j < 200) yr[j] = acc[u];
    }
}

// SpMM + mix fused
__global__ void spmm_mix_k(const int* __restrict__ rowptr, const int* __restrict__ col,
                           const float* __restrict__ val, const float* __restrict__ x,
                           const float* __restrict__ mask, float* __restrict__ y) {
    int r = (blockIdx.x*blockDim.x + threadIdx.x) >> 5;
    int lane = threadIdx.x & 31;
    if (r >= NE) return;
    float acc[7];
    #pragma unroll
    for (int u = 0; u < 7; u++) acc[u] = 0.f;
    int s = rowptr[r], e = rowptr[r+1];
    for (int idx = s; idx < e; idx++) {
        int c = __ldg(&col[idx]);
        float v = __ldg(&val[idx]);
        const float* xr = x + (size_t)c*DIM;
        #pragma unroll
        for (int u = 0; u < 7; u++) {
            int j = lane + 32*u;
            if (j < 200) acc[u] = fmaf(v, xr[j], acc[u]);
        }
    }
    float m = mask[r];
    const float* xr = x + (size_t)r*DIM;
    float* yr = y + (size_t)r*DIM;
    #pragma unroll
    for (int u = 0; u < 7; u++) {
        int j = lane + 32*u;
        if (j < 200) yr[j] = m*xr[j] + (1.f - m)*acc[u];
    }
}

// elementwise mix: y = m*x + (1-m)*mp
__global__ void mix_k(const float* __restrict__ x, const float* __restrict__ mp,
                      const float* __restrict__ mask, float* __restrict__ y) {
    int idx = blockIdx.x*blockDim.x + threadIdx.x;
    if (idx >= NE*DIM) return;
    float m = mask[idx / DIM];
    y[idx] = m*x[idx] + (1.f - m)*mp[idx];
}

// RESCAL -> bf16 hrb directly
__global__ void rescal_k(const float* __restrict__ e0, const float* __restrict__ rel_emb,
                         const int* __restrict__ sub, const int* __restrict__ rel) {
    int b = blockIdx.x;
    int j = threadIdx.x;
    __shared__ float ls[DIM];
    const float* lhs = e0 + (size_t)sub[b]*DIM;
    if (j < DIM) ls[j] = lhs[j];
    __syncthreads();
    if (j < DIM) {
        const float* R = rel_emb + (size_t)rel[b]*RELD;
        float acc = 0.f;
        #pragma unroll 4
        for (int k = 0; k < DIM; k++) acc = fmaf(ls[k], R[(size_t)k*DIM + j], acc);
        g_hrb[(size_t)b*KPAD + j] = __float2bfloat16(acc);
    }
}

// ================= launch ==================================================
extern "C" void kernel_launch(void* const* d_in, const int* in_sizes, int n_in,
                              void* d_out, int out_size) {
    const float* e0       = (const float*)d_in[0];
    const float* rel_emb  = (const float*)d_in[1];
    const float* nW1      = (const float*)d_in[2];
    const float* nb1      = (const float*)d_in[3];
    const float* nW2      = (const float*)d_in[4];
    const float* nb2      = (const float*)d_in[5];
    const float* eW1      = (const float*)d_in[6];
    const float* eb1      = (const float*)d_in[7];
    const float* eW2      = (const float*)d_in[8];
    const float* eb2      = (const float*)d_in[9];
    const int*   adj_row  = (const int*)d_in[10];
    const int*   adj_col  = (const int*)d_in[11];
    const float* adj_val  = (const float*)d_in[12];
    const int*   rw_row   = (const int*)d_in[13];
    const int*   rw_col   = (const int*)d_in[14];
    const float* rw_val   = (const float*)d_in[15];
    const float* node_eps = (const float*)d_in[16];
    const float* edge_eps = (const float*)d_in[17];
    const int*   sub      = (const int*)d_in[18];
    const int*   rel      = (const int*)d_in[19];

    int E   = in_sizes[10];
    int Erw = in_sizes[13];

    float* out        = (float*)d_out;
    float* out_scores = out;
    float* out_xnd    = out + (size_t)BATCH*NE;
    float* out_xed    = out_xnd + (size_t)NE*DIM;

    float *X1, *X2, *MP, *E2, *NMASK, *NEWEDGE;
    int *RPA, *RPR;
    cudaGetSymbolAddress((void**)&X1, g_X1);
    cudaGetSymbolAddress((void**)&X2, g_X2);
    cudaGetSymbolAddress((void**)&MP, g_MP);
    cudaGetSymbolAddress((void**)&E2, g_E2);
    cudaGetSymbolAddress((void**)&NMASK, g_NMASK);
    cudaGetSymbolAddress((void**)&NEWEDGE, g_NEWEDGE);
    cudaGetSymbolAddress((void**)&RPA, g_rp_adj);
    cudaGetSymbolAddress((void**)&RPR, g_rp_rw);

    // streams/events created once, outside capture (first call is correctness run)
    static cudaStream_t s1 = nullptr, s2 = nullptr;
    static cudaEvent_t evFork0, evConv, evRw, evEdge, evMP, evS1, evS2;
    if (!s1) {
        cudaStreamCreateWithFlags(&s1, cudaStreamNonBlocking);
        cudaStreamCreateWithFlags(&s2, cudaStreamNonBlocking);
        cudaEventCreateWithFlags(&evFork0, cudaEventDisableTiming);
        cudaEventCreateWithFlags(&evConv,  cudaEventDisableTiming);
        cudaEventCreateWithFlags(&evRw,    cudaEventDisableTiming);
        cudaEventCreateWithFlags(&evEdge,  cudaEventDisableTiming);
        cudaEventCreateWithFlags(&evMP,    cudaEventDisableTiming);
        cudaEventCreateWithFlags(&evS1,    cudaEventDisableTiming);
        cudaEventCreateWithFlags(&evS2,    cudaEventDisableTiming);
    }

    const int SPB = (NE*32 + 255)/256;
    const int MT  = (NE + 127)/128;

    // ---- fork point (before any work) ----
    cudaEventRecord(evFork0, 0);

    // ---- main stream: prep ----
    rowptr_k<<<(NE+1+255)/256, 256>>>(rw_row, Erw, RPR);
    cudaEventRecord(evRw, 0);
    rowptr_k<<<(NE+1+255)/256, 256>>>(adj_row, E, RPA);
    conv_e0_k<<<(NE*50 + 255)/256, 256>>>(e0);
    cudaEventRecord(evConv, 0);
    dim3 wgrid((DIM*DIM + 255)/256, 4);
    conv_w_k<<<wgrid, 256>>>(nW1, eW1);

    // ---- s1: rescal -> scores (independent chain) ----
    cudaStreamWaitEvent(s1, evFork0, 0);
    rescal_k<<<BATCH, 256, 0, s1>>>(e0, rel_emb, sub, rel);
    cudaStreamWaitEvent(s1, evConv, 0);
    dim3 sgrid((NE + 63)/64, BATCH/128);
    scores_mm_k<<<sgrid, 256, 0, s1>>>(out_scores);
    cudaEventRecord(evS1, s1);

    // ---- s2: edge-branch rw propagation ----
    cudaStreamWaitEvent(s2, evRw, 0);
    spmm_k<<<SPB, 256, 0, s2>>>(RPR, rw_col, rw_val, e0, MP);   // MP = rw@e0 (shared)
    cudaEventRecord(evMP, s2);
    spmm_k<<<SPB, 256, 0, s2>>>(RPR, rw_col, rw_val, MP, E2);   // E2 = rw@MP

    // ---- main: GEMM + gates ----
    dim3 mgrid(MT, 4, 4);
    mm_e0w_k<<<mgrid, 256>>>(nb1, eb1, X1, X2);
    edge_gate_k<<<(E*32 + 255)/256, 256>>>(adj_row, adj_col, adj_val,
                                           eW2 + DIM, eb2 + 1, edge_eps + E, NEWEDGE, E);
    cudaEventRecord(evEdge, 0);
    node_gate_k<<<SPB, 256>>>(X1, nW2,       nb2,     node_eps,      NMASK);
    node_gate_k<<<SPB, 256>>>(X2, nW2 + DIM, nb2 + 1, node_eps + NE, NMASK + NE);

    // ---- s2: final edge spmm (needs E2 + NEWEDGE) ----
    cudaStreamWaitEvent(s2, evEdge, 0);
    spmm_k<<<SPB, 256, 0, s2>>>(RPA, adj_col, NEWEDGE, E2, out_xed);
    cudaEventRecord(evS2, s2);

    // ---- main: node-drop branch (needs MP from s2 + NMASK) ----
    cudaStreamWaitEvent(0, evMP, 0);
    mix_k<<<(NE*DIM + 255)/256, 256>>>(e0, MP, NMASK, X1);
    spmm_k<<<SPB, 256>>>(RPA, adj_col, adj_val, X1, X2);
    spmm_mix_k<<<SPB, 256>>>(RPR, rw_col, rw_val, X2, NMASK + NE, X1);
    spmm_k<<<SPB, 256>>>(RPA, adj_col, adj_val, X1, out_xnd);

    // ---- join ----
    cudaStreamWaitEvent(0, evS1, 0);
    cudaStreamWaitEvent(0, evS2, 0);
}

// round 9
// speedup vs baseline: 1.2725x; 1.0409x over previous
#include <cuda_runtime.h>
#include <cuda_bf16.h>
#include <math.h>
#include <stdint.h>

#define NE    50000
#define DIM   200
#define BATCH 1024
#define EMAX  400000
#define RELD  40000
#define KPAD  256
#define NCHUNK 4
#define NPAD  256

// ---------------- scratch (zero-init => pad regions stay 0)
__device__ __align__(16) __nv_bfloat16 g_e0b[(size_t)NE*KPAD];
__device__ __align__(16) __nv_bfloat16 g_hrb[(size_t)BATCH*KPAD];
__device__ __align__(16) __nv_bfloat16 g_Wtb[(size_t)4*NPAD*KPAD];
__device__ __align__(4) __nv_bfloat16 g_Ub[(size_t)NE*DIM];
__device__ __align__(4) __nv_bfloat16 g_Vb[(size_t)NE*DIM];
__device__ __align__(16) float g_PL[(size_t)2*NE*8];   // node-gate partial dots
__device__ float g_X1[NE*DIM];
__device__ float g_X2[NE*DIM];
__device__ float g_MP[NE*DIM];
__device__ float g_E2[NE*DIM];
__device__ float g_NMASK[2*NE];
__device__ float g_NEWEDGE[EMAX];
__device__ int   g_rp_adj[NE+1];
__device__ int   g_rp_rw [NE+1];

// ================= helpers =================
__device__ __forceinline__ uint32_t smem_u32(const void* p) {
    uint32_t a;
    asm("{ .reg .u64 t; cvta.to.shared.u64 t, %1; cvt.u32.u64 %0, t; }" : "=r"(a) : "l"(p));
    return a;
}
#define SW128(o) ((o) ^ (((o) >> 3) & 0x70))

__device__ __forceinline__ void ldmx4(uint32_t* r, uint32_t addr) {
    asm volatile("ldmatrix.sync.aligned.m8n8.x4.shared.b16 {%0,%1,%2,%3}, [%4];"
        : "=r"(r[0]), "=r"(r[1]), "=r"(r[2]), "=r"(r[3]) : "r"(addr));
}
__device__ __forceinline__ void mma16816(float* c, const uint32_t* a, const uint32_t* b) {
    asm volatile("mma.sync.aligned.m16n8k16.row.col.f32.bf16.bf16.f32 "
        "{%0,%1,%2,%3}, {%4,%5,%6,%7}, {%8,%9}, {%0,%1,%2,%3};"
        : "+f"(c[0]), "+f"(c[1]), "+f"(c[2]), "+f"(c[3])
        : "r"(a[0]), "r"(a[1]), "r"(a[2]), "r"(a[3]), "r"(b[0]), "r"(b[1]));
}
__device__ __forceinline__ void cpa16(uint32_t dst, const void* src) {
    asm volatile("cp.async.cg.shared.global [%0], [%1], 16;" :: "r"(dst), "l"(src));
}
#define CPA_COMMIT() asm volatile("cp.async.commit_group;" ::: "memory")
#define CPA_WAIT(n)  asm volatile("cp.async.wait_group %0;" :: "n"(n) : "memory")

__device__ __forceinline__ float gate_fn(float logits, float u) {
    const float bias = 1e-4f;
    float eps = (2.f*bias - 1.f)*u + (1.f - bias);
    float t = 2.f*(__logf(eps) - __logf(1.f - eps) + logits);
    return 1.f/(1.f + __expf(-t));
}
__device__ __forceinline__ float warp_sum(float v) {
    #pragma unroll
    for (int o = 16; o; o >>= 1) v += __shfl_xor_sync(0xffffffffu, v, o);
    return v;
}

// ================= conversion kernels =================
__global__ void conv_e0_k(const float* __restrict__ e0) {
    int t = blockIdx.x*blockDim.x + threadIdx.x;
    if (t >= NE*50) return;
    int row = t/50, k = (t%50)*4;
    float4 v = *(const float4*)(e0 + (size_t)row*DIM + k);
    __nv_bfloat162 p0, p1;
    p0.x = __float2bfloat16(v.x); p0.y = __float2bfloat16(v.y);
    p1.x = __float2bfloat16(v.z); p1.y = __float2bfloat16(v.w);
    __nv_bfloat16* d = g_e0b + (size_t)row*KPAD + k;
    *(__nv_bfloat162*)(d)     = p0;
    *(__nv_bfloat162*)(d + 2) = p1;
}

__global__ void conv_w_k(const float* __restrict__ nW1, const float* __restrict__ eW1) {
    int inst = blockIdx.y;
    int t = blockIdx.x*blockDim.x + threadIdx.x;
    if (t >= DIM*DIM) return;
    const float* src;
    if (inst == 0)      src = nW1;
    else if (inst == 1) src = nW1 + RELD;
    else if (inst == 2) src = eW1 + 2*RELD;
    else                src = eW1 + 3*RELD;
    int n = t/DIM, k = t%DIM;
    g_Wtb[(size_t)inst*NPAD*KPAD + (size_t)n*KPAD + k] = __float2bfloat16(src[(size_t)k*DIM + n]);
}

// ================= HMMA machinery (R4 geometry) ============================
struct MmaCtx {
    int aAtom0, aAtom1, aLine0, aLine1, aKadd;
    int bAtom0, bAtom1, bLine0, bLine1, bKadd;
};
__device__ __forceinline__ void mma_setup(MmaCtx& cx, int tid) {
    int lane = tid & 31, i = lane >> 3, rr = lane & 7;
    int w = tid >> 5;
    int wm = w >> 1, wn = w & 1;
    int ar0 = wm*32 + (i&1)*8 + rr;
    int ar1 = ar0 + 16;
    int br0 = wn*32 + (i>>1)*8 + rr;
    int br1 = br0 + 16;
    cx.aAtom0 = (ar0>>3)*1024; cx.aLine0 = (ar0&7)*128;
    cx.aAtom1 = (ar1>>3)*1024; cx.aLine1 = (ar1&7)*128;
    cx.aKadd = (i>>1)*16;
    cx.bAtom0 = (br0>>3)*1024; cx.bLine0 = (br0&7)*128;
    cx.bAtom1 = (br1>>3)*1024; cx.bLine1 = (br1&7)*128;
    cx.bKadd = (i&1)*16;
}
__device__ __forceinline__ void mma_chunk(const MmaCtx& cx, uint32_t aA, uint32_t aB,
                                          float acc[2][4][4]) {
    #pragma unroll
    for (int ks = 0; ks < 4; ks++) {
        int kb = ks*32;
        uint32_t a0[4], a1[4], b0[4], b1[4];
        ldmx4(a0, aA + cx.aAtom0 + SW128(cx.aLine0 + kb + cx.aKadd));
        ldmx4(a1, aA + cx.aAtom1 + SW128(cx.aLine1 + kb + cx.aKadd));
        ldmx4(b0, aB + cx.bAtom0 + SW128(cx.bLine0 + kb + cx.bKadd));
        ldmx4(b1, aB + cx.bAtom1 + SW128(cx.bLine1 + kb + cx.bKadd));
        mma16816(acc[0][0], a0, b0);
        mma16816(acc[0][1], a0, b0 + 2);
        mma16816(acc[0][2], a0, b1);
        mma16816(acc[0][3], a0, b1 + 2);
        mma16816(acc[1][0], a1, b0);
        mma16816(acc[1][1], a1, b0 + 2);
        mma16816(acc[1][2], a1, b1);
        mma16816(acc[1][3], a1, b1 + 2);
    }
}
__device__ __forceinline__ void load_a128_async(uint32_t sA, const __nv_bfloat16* Ag,
                                                int row0, int rmax, int c, int tid) {
    #pragma unroll
    for (int i = 0; i < 4; i++) {
        int idx = tid + i*256;
        int r = idx >> 3, q = idx & 7;
        int gr = row0 + r; if (gr >= rmax) gr = 0;
        uint32_t off = (uint32_t)((r>>3)*1024) + SW128((uint32_t)((r&7)*128 + q*16));
        cpa16(sA + off, Ag + (size_t)gr*KPAD + c*64 + q*8);
    }
}
__device__ __forceinline__ void load_b64_async(uint32_t sB, const __nv_bfloat16* Bg,
                                               int row0, int rmax, int c, int tid) {
    #pragma unroll
    for (int i = 0; i < 2; i++) {
        int idx = tid + i*256;
        int r = idx >> 3, q = idx & 7;
        int gr = row0 + r; if (gr >= rmax) gr = 0;
        uint32_t off = (uint32_t)((r>>3)*1024) + SW128((uint32_t)((r&7)*128 + q*16));
        cpa16(sB + off, Bg + (size_t)gr*KPAD + c*64 + q*8);
    }
}

// ================= GEMM 1: e0 @ W (4 instances); node-gate dots fused ======
__global__ void __launch_bounds__(256) mm_e0w_k(
    const float* __restrict__ nb1, const float* __restrict__ eb1,
    const float* __restrict__ nW2)
{
    __shared__ __align__(1024) uint8_t sA[2][16384];
    __shared__ __align__(1024) uint8_t sB[2][8192];
    int bm = blockIdx.x, nt64 = blockIdx.y, inst = blockIdx.z;
    int tid = threadIdx.x;
    uint32_t aA0 = smem_u32(sA[0]), aA1 = smem_u32(sA[1]);
    uint32_t aB0 = smem_u32(sB[0]), aB1 = smem_u32(sB[1]);

    MmaCtx cx; mma_setup(cx, tid);
    float acc[2][4][4];
    #pragma unroll
    for (int a = 0; a < 2; a++)
        #pragma unroll
        for (int b = 0; b < 4; b++)
            #pragma unroll
            for (int q = 0; q < 4; q++) acc[a][b][q] = 0.f;

    const __nv_bfloat16* Bg = g_Wtb + (size_t)inst*NPAD*KPAD;

    load_a128_async(aA0, g_e0b, bm*128, NE, 0, tid);
    load_b64_async (aB0, Bg, nt64*64, NPAD, 0, tid);
    CPA_COMMIT();
    #pragma unroll
    for (int c = 0; c < NCHUNK; c++) {
        uint32_t curA = (c & 1) ? aA1 : aA0, curB = (c & 1) ? aB1 : aB0;
        if (c + 1 < NCHUNK) {
            uint32_t nxtA = ((c+1) & 1) ? aA1 : aA0, nxtB = ((c+1) & 1) ? aB1 : aB0;
            load_a128_async(nxtA, g_e0b, bm*128, NE, c+1, tid);
            load_b64_async (nxtB, Bg, nt64*64, NPAD, c+1, tid);
            CPA_COMMIT();
            CPA_WAIT(1);
        } else {
            CPA_WAIT(0);
        }
        __syncthreads();
        mma_chunk(cx, curA, curB, acc);
        __syncthreads();
    }

    int lane = tid & 31, w = tid >> 5;
    int wm = w >> 1, wn = w & 1;
    int mrow = lane >> 2, ncol = (lane & 3)*2;
    int nbase = nt64*64 + wn*32;

    if (inst < 2) {
        // fused node-gate partial dot: relu(acc+b1) . W2 over this 32-col segment
        const float* bias = nb1 + inst*DIM;
        const float* W2 = nW2 + inst*DIM;
        int seg = nt64*2 + wn;   // 0..7
        #pragma unroll
        for (int mt = 0; mt < 2; mt++) {
            float p0 = 0.f, p1 = 0.f;
            #pragma unroll
            for (int nt = 0; nt < 4; nt++) {
                int n = nbase + nt*8 + ncol;
                float b0 = 0.f, b1v = 0.f, w0 = 0.f, w1 = 0.f;
                if (n < DIM)     { b0 = bias[n];   w0 = W2[n];   }
                if (n + 1 < DIM) { b1v = bias[n+1]; w1 = W2[n+1]; }
                p0 = fmaf(fmaxf(acc[mt][nt][0] + b0, 0.f), w0, p0);
                p0 = fmaf(fmaxf(acc[mt][nt][1] + b1v, 0.f), w1, p0);
                p1 = fmaf(fmaxf(acc[mt][nt][2] + b0, 0.f), w0, p1);
                p1 = fmaf(fmaxf(acc[mt][nt][3] + b1v, 0.f), w1, p1);
            }
            // reduce across the 4 lanes sharing a row (lane&3)
            p0 += __shfl_xor_sync(0xffffffffu, p0, 1);
            p0 += __shfl_xor_sync(0xffffffffu, p0, 2);
            p1 += __shfl_xor_sync(0xffffffffu, p1, 1);
            p1 += __shfl_xor_sync(0xffffffffu, p1, 2);
            if ((lane & 3) == 0) {
                int m0 = bm*128 + wm*32 + mt*16 + mrow;
                if (m0 < NE)     g_PL[((size_t)inst*NE + m0)*8 + seg] = p0;
                if (m0 + 8 < NE) g_PL[((size_t)inst*NE + m0 + 8)*8 + seg] = p1;
            }
        }
    } else {
        __nv_bfloat16* C = (inst == 2) ? g_Ub : g_Vb;
        const float* bias = (inst == 3) ? (eb1 + DIM) : nullptr;
        #pragma unroll
        for (int mt = 0; mt < 2; mt++) {
            int m = bm*128 + wm*32 + mt*16 + mrow;
            if (m >= NE) continue;
            #pragma unroll
            for (int nt = 0; nt < 4; nt++) {
                int n = nbase + nt*8 + ncol;
                if (n >= DIM) continue;
                float b0 = bias ? bias[n] : 0.f, b1 = bias ? bias[n+1] : 0.f;
                __nv_bfloat162 p, q;
                p.x = __float2bfloat16(acc[mt][nt][0] + b0);
                p.y = __float2bfloat16(acc[mt][nt][1] + b1);
                q.x = __float2bfloat16(acc[mt][nt][2] + b0);
                q.y = __float2bfloat16(acc[mt][nt][3] + b1);
                *(__nv_bfloat162*)(C + (size_t)m*DIM + n) = p;
                if (m + 8 < NE) *(__nv_bfloat162*)(C + (size_t)(m+8)*DIM + n) = q;
            }
        }
    }
}

// gate finalize: sum 8 partials, apply gate
__global__ void gate_fin_k(const float* __restrict__ nb2, const float* __restrict__ eps,
                           float* __restrict__ mask) {
    int idx = blockIdx.x*blockDim.x + threadIdx.x;
    if (idx >= 2*NE) return;
    int inst = idx / NE;
    const float* p = g_PL + (size_t)idx*8;
    float4 a = *(const float4*)p;
    float4 b = *(const float4*)(p + 4);
    float s = ((a.x + a.y) + (a.z + a.w)) + ((b.x + b.y) + (b.z + b.w));
    mask[idx] = gate_fn(s + nb2[inst], eps[idx]);
}

// ================= GEMM 2: scores ==========================================
__global__ void __launch_bounds__(256) scores_mm_k(float* __restrict__ out)
{
    __shared__ __align__(1024) uint8_t sA[2][16384];
    __shared__ __align__(1024) uint8_t sB[2][8192];
    int bx = blockIdx.x, by = blockIdx.y;
    int tid = threadIdx.x;
    uint32_t aA0 = smem_u32(sA[0]), aA1 = smem_u32(sA[1]);
    uint32_t aB0 = smem_u32(sB[0]), aB1 = smem_u32(sB[1]);

    MmaCtx cx; mma_setup(cx, tid);
    float acc[2][4][4];
    #pragma unroll
    for (int a = 0; a < 2; a++)
        #pragma unroll
        for (int b = 0; b < 4; b++)
            #pragma unroll
            for (int q = 0; q < 4; q++) acc[a][b][q] = 0.f;

    load_a128_async(aA0, g_hrb, by*128, BATCH, 0, tid);
    load_b64_async (aB0, g_e0b, bx*64, NE, 0, tid);
    CPA_COMMIT();
    #pragma unroll
    for (int c = 0; c < NCHUNK; c++) {
        uint32_t curA = (c & 1) ? aA1 : aA0, curB = (c & 1) ? aB1 : aB0;
        if (c + 1 < NCHUNK) {
            uint32_t nxtA = ((c+1) & 1) ? aA1 : aA0, nxtB = ((c+1) & 1) ? aB1 : aB0;
            load_a128_async(nxtA, g_hrb, by*128, BATCH, c+1, tid);
            load_b64_async (nxtB, g_e0b, bx*64, NE, c+1, tid);
            CPA_COMMIT();
            CPA_WAIT(1);
        } else {
            CPA_WAIT(0);
        }
        __syncthreads();
        mma_chunk(cx, curA, curB, acc);
        __syncthreads();
    }

    int lane = tid & 31, w = tid >> 5;
    int wm = w >> 1, wn = w & 1;
    int mrow = lane >> 2, ncol = (lane & 3)*2;
    #pragma unroll
    for (int mt = 0; mt < 2; mt++) {
        int m = by*128 + wm*32 + mt*16 + mrow;
        #pragma unroll
        for (int nt = 0; nt < 4; nt++) {
            int n = bx*64 + wn*32 + nt*8 + ncol;
            if (n < NE) {
                float2 v01, v23;
                v01.x = 1.f/(1.f + __expf(-acc[mt][nt][0]));
                v01.y = 1.f/(1.f + __expf(-acc[mt][nt][1]));
                v23.x = 1.f/(1.f + __expf(-acc[mt][nt][2]));
                v23.y = 1.f/(1.f + __expf(-acc[mt][nt][3]));
                *(float2*)(out + (size_t)m*NE + n) = v01;
                *(float2*)(out + (size_t)(m+8)*NE + n) = v23;
            }
        }
    }
}

// ================= support kernels =================
__global__ void rowptr_k(const int* __restrict__ row, int nnz, int* __restrict__ rowptr) {
    int n = blockIdx.x*blockDim.x + threadIdx.x;
    if (n > NE) return;
    int lo = 0, hi = nnz;
    while (lo < hi) { int mid = (lo+hi) >> 1; if (row[mid] < n) lo = mid+1; else hi = mid; }
    rowptr[n] = lo;
}

__global__ void edge_gate_k(const int* __restrict__ row, const int* __restrict__ col,
                            const float* __restrict__ adj_val,
                            const float* __restrict__ W2, const float* __restrict__ b2,
                            const float* __restrict__ eps, float* __restrict__ new_edge,
                            int E) {
    int e = (blockIdx.x*blockDim.x + threadIdx.x) >> 5;
    int lane = threadIdx.x & 31;
    if (e >= E) return;
    int r = row[e], c = col[e];
    const __nv_bfloat162* ur = (const __nv_bfloat162*)(g_Ub + (size_t)r*DIM);
    const __nv_bfloat162* vr = (const __nv_bfloat162*)(g_Vb + (size_t)c*DIM);
    float acc = 0.f;
    #pragma unroll
    for (int u = 0; u < 4; u++) {
        int p = lane + 32*u;
        if (p < 100) {
            __nv_bfloat162 uv = ur[p], vv = vr[p];
            float h0 = fmaxf(__bfloat162float(uv.x) + __bfloat162float(vv.x), 0.f);
            float h1 = fmaxf(__bfloat162float(uv.y) + __bfloat162float(vv.y), 0.f);
            acc = fmaf(h0, W2[2*p], acc);
            acc = fmaf(h1, W2[2*p+1], acc);
        }
    }
    acc = warp_sum(acc);
    if (lane == 0) new_edge[e] = adj_val[e] * gate_fn(acc + b2[0], eps[e]);
}

__global__ void spmm_k(const int* __restrict__ rowptr, const int* __restrict__ col,
                       const float* __restrict__ val, const float* __restrict__ x,
                       float* __restrict__ y) {
    int r = (blockIdx.x*blockDim.x + threadIdx.x) >> 5;
    int lane = threadIdx.x & 31;
    if (r >= NE) return;
    float acc[7];
    #pragma unroll
    for (int u = 0; u < 7; u++) acc[u] = 0.f;
    int s = rowptr[r], e = rowptr[r+1];
    for (int idx = s; idx < e; idx++) {
        int c = __ldg(&col[idx]);
        float v = __ldg(&val[idx]);
        const float* xr = x + (size_t)c*DIM;
        #pragma unroll
        for (int u = 0; u < 7; u++) {
            int j = lane + 32*u;
            if (j < 200) acc[u] = fmaf(v, xr[j], acc[u]);
        }
    }
    float* yr = y + (size_t)r*DIM;
    #pragma unroll
    for (int u = 0; u < 7; u++) {
        int j = lane + 32*u;
        if (j < 200) yr[j] = acc[u];
    }
}

__global__ void spmm_mix_k(const int* __restrict__ rowptr, const int* __restrict__ col,
                           const float* __restrict__ val, const float* __restrict__ x,
                           const float* __restrict__ mask, float* __restrict__ y) {
    int r = (blockIdx.x*blockDim.x + threadIdx.x) >> 5;
    int lane = threadIdx.x & 31;
    if (r >= NE) return;
    float acc[7];
    #pragma unroll
    for (int u = 0; u < 7; u++) acc[u] = 0.f;
    int s = rowptr[r], e = rowptr[r+1];
    for (int idx = s; idx < e; idx++) {
        int c = __ldg(&col[idx]);
        float v = __ldg(&val[idx]);
        const float* xr = x + (size_t)c*DIM;
        #pragma unroll
        for (int u = 0; u < 7; u++) {
            int j = lane + 32*u;
            if (j < 200) acc[u] = fmaf(v, xr[j], acc[u]);
        }
    }
    float m = mask[r];
    const float* xr = x + (size_t)r*DIM;
    float* yr = y + (size_t)r*DIM;
    #pragma unroll
    for (int u = 0; u < 7; u++) {
        int j = lane + 32*u;
        if (j < 200) yr[j] = m*xr[j] + (1.f - m)*acc[u];
    }
}

__global__ void mix_k(const float* __restrict__ x, const float* __restrict__ mp,
                      const float* __restrict__ mask, float* __restrict__ y) {
    int idx = blockIdx.x*blockDim.x + threadIdx.x;
    if (idx >= NE*DIM) return;
    float m = mask[idx / DIM];
    y[idx] = m*x[idx] + (1.f - m)*mp[idx];
}

__global__ void rescal_k(const float* __restrict__ e0, const float* __restrict__ rel_emb,
                         const int* __restrict__ sub, const int* __restrict__ rel) {
    int b = blockIdx.x;
    int j = threadIdx.x;
    __shared__ float ls[DIM];
    const float* lhs = e0 + (size_t)sub[b]*DIM;
    if (j < DIM) ls[j] = lhs[j];
    __syncthreads();
    if (j < DIM) {
        const float* R = rel_emb + (size_t)rel[b]*RELD;
        float acc = 0.f;
        #pragma unroll 4
        for (int k = 0; k < DIM; k++) acc = fmaf(ls[k], R[(size_t)k*DIM + j], acc);
        g_hrb[(size_t)b*KPAD + j] = __float2bfloat16(acc);
    }
}

// ================= launch ==================================================
extern "C" void kernel_launch(void* const* d_in, const int* in_sizes, int n_in,
                              void* d_out, int out_size) {
    const float* e0       = (const float*)d_in[0];
    const float* rel_emb  = (const float*)d_in[1];
    const float* nW1      = (const float*)d_in[2];
    const float* nb1      = (const float*)d_in[3];
    const float* nW2      = (const float*)d_in[4];
    const float* nb2      = (const float*)d_in[5];
    const float* eW1      = (const float*)d_in[6];
    const float* eb1      = (const float*)d_in[7];
    const float* eW2      = (const float*)d_in[8];
    const float* eb2      = (const float*)d_in[9];
    const int*   adj_row  = (const int*)d_in[10];
    const int*   adj_col  = (const int*)d_in[11];
    const float* adj_val  = (const float*)d_in[12];
    const int*   rw_row   = (const int*)d_in[13];
    const int*   rw_col   = (const int*)d_in[14];
    const float* rw_val   = (const float*)d_in[15];
    const float* node_eps = (const float*)d_in[16];
    const float* edge_eps = (const float*)d_in[17];
    const int*   sub      = (const int*)d_in[18];
    const int*   rel      = (const int*)d_in[19];

    int E   = in_sizes[10];
    int Erw = in_sizes[13];

    float* out        = (float*)d_out;
    float* out_scores = out;
    float* out_xnd    = out + (size_t)BATCH*NE;
    float* out_xed    = out_xnd + (size_t)NE*DIM;

    float *X1, *X2, *MP, *E2, *NMASK, *NEWEDGE;
    int *RPA, *RPR;
    cudaGetSymbolAddress((void**)&X1, g_X1);
    cudaGetSymbolAddress((void**)&X2, g_X2);
    cudaGetSymbolAddress((void**)&MP, g_MP);
    cudaGetSymbolAddress((void**)&E2, g_E2);
    cudaGetSymbolAddress((void**)&NMASK, g_NMASK);
    cudaGetSymbolAddress((void**)&NEWEDGE, g_NEWEDGE);
    cudaGetSymbolAddress((void**)&RPA, g_rp_adj);
    cudaGetSymbolAddress((void**)&RPR, g_rp_rw);

    static cudaStream_t s1 = nullptr, s2 = nullptr;
    static cudaEvent_t evFork0, evConv, evRw, evMM, evMP, evS1, evS2;
    if (!s1) {
        cudaStreamCreateWithFlags(&s1, cudaStreamNonBlocking);
        cudaStreamCreateWithFlags(&s2, cudaStreamNonBlocking);
        cudaEventCreateWithFlags(&evFork0, cudaEventDisableTiming);
        cudaEventCreateWithFlags(&evConv,  cudaEventDisableTiming);
        cudaEventCreateWithFlags(&evRw,    cudaEventDisableTiming);
        cudaEventCreateWithFlags(&evMM,    cudaEventDisableTiming);
        cudaEventCreateWithFlags(&evMP,    cudaEventDisableTiming);
        cudaEventCreateWithFlags(&evS1,    cudaEventDisableTiming);
        cudaEventCreateWithFlags(&evS2,    cudaEventDisableTiming);
    }

    const int SPB = (NE*32 + 255)/256;
    const int MT  = (NE + 127)/128;

    // ---- fork point ----
    cudaEventRecord(evFork0, 0);

    // ---- main stream: prep ----
    rowptr_k<<<(NE+1+255)/256, 256>>>(rw_row, Erw, RPR);
    cudaEventRecord(evRw, 0);
    rowptr_k<<<(NE+1+255)/256, 256>>>(adj_row, E, RPA);
    conv_e0_k<<<(NE*50 + 255)/256, 256>>>(e0);
    cudaEventRecord(evConv, 0);
    dim3 wgrid((DIM*DIM + 255)/256, 4);
    conv_w_k<<<wgrid, 256>>>(nW1, eW1);

    // ---- s1: rescal -> scores ----
    cudaStreamWaitEvent(s1, evFork0, 0);
    rescal_k<<<BATCH, 256, 0, s1>>>(e0, rel_emb, sub, rel);
    cudaStreamWaitEvent(s1, evConv, 0);
    dim3 sgrid((NE + 63)/64, BATCH/128);
    scores_mm_k<<<sgrid, 256, 0, s1>>>(out_scores);
    cudaEventRecord(evS1, s1);

    // ---- s2: edge-branch rw propagation ----
    cudaStreamWaitEvent(s2, evRw, 0);
    spmm_k<<<SPB, 256, 0, s2>>>(RPR, rw_col, rw_val, e0, MP);
    cudaEventRecord(evMP, s2);
    spmm_k<<<SPB, 256, 0, s2>>>(RPR, rw_col, rw_val, MP, E2);

    // ---- main: GEMM (with fused node-gate dots) + finalize ----
    dim3 mgrid(MT, 4, 4);
    mm_e0w_k<<<mgrid, 256>>>(nb1, eb1, nW2);
    cudaEventRecord(evMM, 0);
    gate_fin_k<<<(2*NE + 255)/256, 256>>>(nb2, node_eps, NMASK);

    // ---- s2: edge gate + final edge spmm ----
    cudaStreamWaitEvent(s2, evMM, 0);
    edge_gate_k<<<(E*32 + 255)/256, 256, 0, s2>>>(adj_row, adj_col, adj_val,
                                                  eW2 + DIM, eb2 + 1, edge_eps + E, NEWEDGE, E);
    spmm_k<<<SPB, 256, 0, s2>>>(RPA, adj_col, NEWEDGE, E2, out_xed);
    cudaEventRecord(evS2, s2);

    // ---- main: node-drop branch ----
    cudaStreamWaitEvent(0, evMP, 0);
    mix_k<<<(NE*DIM + 255)/256, 256>>>(e0, MP, NMASK, X1);
    spmm_k<<<SPB, 256>>>(RPA, adj_col, adj_val, X1, X2);
    spmm_mix_k<<<SPB, 256>>>(RPR, rw_col, rw_val, X2, NMASK + NE, X1);
    spmm_k<<<SPB, 256>>>(RPA, adj_col, adj_val, X1, out_xnd);

    // ---- join ----
    cudaStreamWaitEvent(0, evS1, 0);
    cudaStreamWaitEvent(0, evS2, 0);
}